// round 4
// baseline (speedup 1.0000x reference)
#include <cuda_runtime.h>

#define DEV __device__ __forceinline__
typedef unsigned long long ull;

#define B_ 1024
#define U_ 512
#define SIGD 16512

// ---------- scratch ----------
__device__ float d_mu[B_];
__device__ float d_rstd[B_];
__device__ float d_skip[B_ * 3];
__device__ float d_sigw[B_ * 3];
__device__ __align__(16) float d_z[B_ * 1536];
__device__ __align__(16) float d_h1[B_ * U_];
__device__ __align__(16) float d_aggin[3 * B_ * 128];
__device__ __align__(16) float d_subE[3 * B_ * 1152];
__device__ __align__(16) float d_subW[3 * 1152 * 128];
__device__ __align__(16) float d_agg[B_ * 384];

// ---------- helpers ----------
DEV float sigm(float x) { return 1.f / (1.f + __expf(-x)); }

DEV ull dup2(float x) { ull r; asm("mov.b64 %0,{%1,%1};" : "=l"(r) : "f"(x)); return r; }
DEV void fma2(ull& d, ull a, ull b) { asm("fma.rn.f32x2 %0,%1,%2,%0;" : "+l"(d) : "l"(a), "l"(b)); }
DEV float2 unpk(ull p) { float lo, hi; asm("mov.b64 {%0,%1},%2;" : "=f"(lo), "=f"(hi) : "l"(p)); return make_float2(lo, hi); }

// silu + 8 cubic B-spline bases; knots -2.2 + 0.4k
DEV void kan_expand(float xn, float e[9]) {
    e[0] = xn * sigm(xn);
#pragma unroll
    for (int j = 1; j < 9; j++) e[j] = 0.f;
    float tp = (xn + 2.2f) * 2.5f;
    float tf = floorf(tp);
    if (tf >= 0.f && tf <= 10.f) {
        int t = (int)tf;
        float u = tp - tf, u2 = u * u, u3 = u2 * u, omu = 1.f - u;
        float v0 = omu * omu * omu * (1.f / 6.f);
        float v1 = (3.f * u3 - 6.f * u2 + 4.f) * (1.f / 6.f);
        float v2 = (-3.f * u3 + 3.f * u2 + 3.f * u + 1.f) * (1.f / 6.f);
        float v3 = u3 * (1.f / 6.f);
        if (t >= 3)           e[t - 2] = v0;
        if (t >= 2 && t <= 9) e[t - 1] = v1;
        if (t >= 1 && t <= 8) e[t]     = v2;
        if (t <= 7)           e[t + 1] = v3;
    }
}

DEV float red128(float v, float* sh) {
    int t = threadIdx.x;
    sh[t] = v; __syncthreads();
#pragma unroll
    for (int s = 64; s > 0; s >>= 1) { if (t < s) sh[t] += sh[t + s]; __syncthreads(); }
    float r = sh[0]; __syncthreads();
    return r;
}

// ---------- K1: sig LN stats (closed form) + skip ----------
__global__ __launch_bounds__(128) void k_stats(const float* __restrict__ x,
                                               const float* __restrict__ skw,
                                               const float* __restrict__ skb) {
    __shared__ float xs[128], sh[128];
    int b = blockIdx.x, t = threadIdx.x;
    float xv = x[b * 128 + t];
    xs[t] = xv; __syncthreads();
    float S = red128(xv, sh);
    float Q = red128(xv * xv, sh);
    if (t == 0) {
        float mean = (S + 0.5f * S * S) / (float)SIGD;
        float m2 = (Q + 0.25f * Q * Q) / (float)SIGD;
        d_mu[b] = mean;
        d_rstd[b] = rsqrtf(m2 - mean * mean + 1e-3f);
    }
    float a0 = 0.f, a1 = 0.f, a2 = 0.f;
    for (int i = t; i < SIGD; i += 128) {
        float sv = (i < 128) ? xs[i] : 0.5f * xs[(i - 128) >> 7] * xs[(i - 128) & 127];
        a0 += sv * skw[i * 3 + 0];
        a1 += sv * skw[i * 3 + 1];
        a2 += sv * skw[i * 3 + 2];
    }
    a0 = red128(a0, sh); a1 = red128(a1, sh); a2 = red128(a2, sh);
    if (t == 0) {
        d_skip[b * 3 + 0] = a0 + skb[0];
        d_skip[b * 3 + 1] = a1 + skb[1];
        d_skip[b * 3 + 2] = a2 + skb[2];
    }
}

// ---------- K2: the big KAN GEMM (sig -> h1) ----------
// grid (8,16): 64 cols x 64 rows per block. K = 16512 features * 9.
__global__ __launch_bounds__(256) void k_kan1(const float* __restrict__ x,
                                              const float* __restrict__ lng,
                                              const float* __restrict__ lnb,
                                              const float* __restrict__ wb,
                                              const float* __restrict__ ws) {
    extern __shared__ float sm[];
    float* xs = sm;                 // 64*128
    float* As = sm + 8192;          // 72*64
    float* Bs = sm + 8192 + 4608;   // 72*64
    float* mus = sm + 8192 + 9216;  // 64
    float* rss = mus + 64;          // 64
    int tid = threadIdx.x;
    int rowBase = blockIdx.y * 64, colBase = blockIdx.x * 64;

    for (int idx = tid; idx < 8192; idx += 256)
        xs[idx] = x[(rowBase + (idx >> 7)) * 128 + (idx & 127)];
    if (tid < 64) { mus[tid] = d_mu[rowBase + tid]; rss[tid] = d_rstd[rowBase + tid]; }
    __syncthreads();

    int r0 = (tid >> 4) * 4, c0 = (tid & 15) * 4;
    ull acc[2][4] = {};
    float4 w[5];

#define LOADW(CH) {                                                          \
    int f0_ = (CH) * 8;                                                      \
    _Pragma("unroll")                                                        \
    for (int m = 0; m < 5; m++) {                                            \
        int idx = tid + m * 256;                                             \
        if (idx < 1152) {                                                    \
            int kk = idx >> 4, c4 = (idx & 15) << 2;                         \
            int fi = kk / 9, j = kk - fi * 9;                                \
            size_t i = (size_t)(f0_ + fi);                                   \
            const float* p = (j == 0) ? wb + i * 512 + colBase + c4          \
                                      : ws + (i * 8 + (j - 1)) * 512 + colBase + c4; \
            w[m] = *(const float4*)p;                                        \
        }                                                                    \
    } }

    LOADW(0)
    for (int ch = 0; ch < 2064; ch++) {
#pragma unroll
        for (int m = 0; m < 5; m++) {
            int idx = tid + m * 256;
            if (idx < 1152) {
                int kk = idx >> 4, c4 = (idx & 15) << 2;
                *(float4*)&Bs[kk * 64 + c4] = w[m];
            }
        }
#pragma unroll
        for (int t2 = tid; t2 < 512; t2 += 256) {
            int f = t2 >> 6, b = t2 & 63;
            int i = ch * 8 + f;
            float val = (i < 128) ? xs[b * 128 + i]
                                  : 0.5f * xs[b * 128 + ((i - 128) >> 7)] * xs[b * 128 + ((i - 128) & 127)];
            float xn = (val - mus[b]) * rss[b] * __ldg(lng + i) + __ldg(lnb + i);
            float e[9];
            kan_expand(xn, e);
#pragma unroll
            for (int j = 0; j < 9; j++) As[(f * 9 + j) * 64 + b] = e[j];
        }
        if (ch + 1 < 2064) LOADW(ch + 1)
        __syncthreads();
#pragma unroll 8
        for (int k = 0; k < 72; k++) {
            const float* ap = &As[k * 64 + r0];
            ull a0 = *(const ull*)ap;
            ull a1 = *(const ull*)(ap + 2);
            float4 b4 = *(const float4*)&Bs[k * 64 + c0];
            ull b0 = dup2(b4.x), b1 = dup2(b4.y), b2 = dup2(b4.z), b3 = dup2(b4.w);
            fma2(acc[0][0], a0, b0); fma2(acc[0][1], a0, b1);
            fma2(acc[0][2], a0, b2); fma2(acc[0][3], a0, b3);
            fma2(acc[1][0], a1, b0); fma2(acc[1][1], a1, b1);
            fma2(acc[1][2], a1, b2); fma2(acc[1][3], a1, b3);
        }
        __syncthreads();
    }
#undef LOADW
#pragma unroll
    for (int p = 0; p < 2; p++)
#pragma unroll
        for (int c = 0; c < 4; c++) {
            float2 v = unpk(acc[p][c]);
            int row = rowBase + r0 + 2 * p, col = colBase + c0 + c;
            d_h1[row * 512 + col] = v.x;
            d_h1[(row + 1) * 512 + col] = v.y;
        }
}

// ---------- K3: head — kan2 (512->3), GLU, LN, softmax -> sig weights ----------
__global__ __launch_bounds__(128) void k_head(const float* __restrict__ g2g,
                                              const float* __restrict__ g2b,
                                              const float* __restrict__ k2base,
                                              const float* __restrict__ k2spl,
                                              const float* __restrict__ gw, const float* __restrict__ gb,
                                              const float* __restrict__ sw, const float* __restrict__ sb,
                                              const float* __restrict__ lg, const float* __restrict__ lb) {
    __shared__ float sh[128];
    int b = blockIdx.x, t = threadIdx.x;
    float v[4], S = 0.f, Q = 0.f;
#pragma unroll
    for (int m = 0; m < 4; m++) {
        v[m] = d_h1[b * 512 + t + 128 * m];
        S += v[m]; Q += v[m] * v[m];
    }
    S = red128(S, sh); Q = red128(Q, sh);
    float mean = S / 512.f;
    float rstd = rsqrtf(Q / 512.f - mean * mean + 1e-3f);
    float a0 = 0.f, a1 = 0.f, a2 = 0.f;
#pragma unroll
    for (int m = 0; m < 4; m++) {
        int i = t + 128 * m;
        float xn = (v[m] - mean) * rstd * g2g[i] + g2b[i];
        float e[9];
        kan_expand(xn, e);
        a0 += e[0] * k2base[i * 3 + 0];
        a1 += e[0] * k2base[i * 3 + 1];
        a2 += e[0] * k2base[i * 3 + 2];
#pragma unroll
        for (int j = 0; j < 8; j++) {
            const float* sp = k2spl + (size_t)(i * 8 + j) * 3;
            a0 += e[1 + j] * sp[0];
            a1 += e[1 + j] * sp[1];
            a2 += e[1 + j] * sp[2];
        }
    }
    a0 = red128(a0, sh); a1 = red128(a1, sh); a2 = red128(a2, sh);
    if (t == 0) {
        float h2[3] = {a0, a1, a2};
        float y[3];
#pragma unroll
        for (int o = 0; o < 3; o++) {
            float g1 = gb[o], s1 = sb[o];
#pragma unroll
            for (int p = 0; p < 3; p++) { g1 += h2[p] * gw[p * 3 + o]; s1 += h2[p] * sw[p * 3 + o]; }
            y[o] = d_skip[b * 3 + o] + g1 * sigm(s1);
        }
        float m = (y[0] + y[1] + y[2]) * (1.f / 3.f);
        float var = ((y[0] - m) * (y[0] - m) + (y[1] - m) * (y[1] - m) + (y[2] - m) * (y[2] - m)) * (1.f / 3.f);
        float rs = rsqrtf(var + 1e-3f);
        float yn[3], mx = -1e30f;
#pragma unroll
        for (int o = 0; o < 3; o++) { yn[o] = (y[o] - m) * rs * lg[o] + lb[o]; mx = fmaxf(mx, yn[o]); }
        float e0 = __expf(yn[0] - mx), e1 = __expf(yn[1] - mx), e2 = __expf(yn[2] - mx);
        float inv = 1.f / (e0 + e1 + e2);
        d_sigw[b * 3 + 0] = e0 * inv;
        d_sigw[b * 3 + 1] = e1 * inv;
        d_sigw[b * 3 + 2] = e2 * inv;
    }
}

// ---------- K4: LSTM gates z = sigmoid([x|h0]@[W;R] + bias) ----------
__global__ __launch_bounds__(256) void k_z(const float* __restrict__ x, const float* __restrict__ h0,
                                           const float* __restrict__ W1, const float* __restrict__ W2,
                                           const float* __restrict__ bias) {
    __shared__ float As[16 * 64], Bs[16 * 64];
    int tid = threadIdx.x;
    int rowBase = blockIdx.y * 64, colBase = blockIdx.x * 64;
    int r0 = (tid >> 4) * 4, c0 = (tid & 15) * 4;
    float acc[4][4] = {};
    for (int kt = 0; kt < 640; kt += 16) {
        for (int idx = tid; idx < 1024; idx += 256) {
            int kk = idx & 15, m = idx >> 4, kg = kt + kk, b = rowBase + m;
            As[kk * 64 + m] = (kg < 128) ? x[b * 128 + kg] : h0[b * 512 + kg - 128];
            int cc = idx & 63, k2 = idx >> 6, kg2 = kt + k2, c = colBase + cc;
            Bs[k2 * 64 + cc] = (kg2 < 128) ? W1[kg2 * 1536 + c] : W2[(size_t)(kg2 - 128) * 1536 + c];
        }
        __syncthreads();
#pragma unroll
        for (int k = 0; k < 16; k++) {
            float4 a = *(const float4*)&As[k * 64 + r0];
            float4 bb = *(const float4*)&Bs[k * 64 + c0];
            float av[4] = {a.x, a.y, a.z, a.w}, bv[4] = {bb.x, bb.y, bb.z, bb.w};
#pragma unroll
            for (int i = 0; i < 4; i++)
#pragma unroll
                for (int j = 0; j < 4; j++) acc[i][j] += av[i] * bv[j];
        }
        __syncthreads();
    }
#pragma unroll
    for (int i = 0; i < 4; i++)
#pragma unroll
        for (int j = 0; j < 4; j++) {
            int b = rowBase + r0 + i, c = colBase + c0 + j;
            d_z[b * 1536 + c] = sigm(acc[i][j] + bias[c]);
        }
}

// ---------- K5: agg_in = x@rk_in[n] + sub_states[n]@rk_st[n] ----------
__global__ __launch_bounds__(256) void k_aggin(const float* __restrict__ x, const float* __restrict__ ss,
                                               const float* __restrict__ rki, const float* __restrict__ rks) {
    __shared__ float As[16 * 64], Bs[16 * 64];
    int tid = threadIdx.x, n = blockIdx.z;
    int rowBase = blockIdx.y * 64, colBase = blockIdx.x * 64;
    int r0 = (tid >> 4) * 4, c0 = (tid & 15) * 4;
    float acc[4][4] = {};
    for (int kt = 0; kt < 256; kt += 16) {
        for (int idx = tid; idx < 1024; idx += 256) {
            int kk = idx & 15, m = idx >> 4, kg = kt + kk, b = rowBase + m;
            As[kk * 64 + m] = (kg < 128) ? x[b * 128 + kg] : ss[n * 131072 + b * 128 + kg - 128];
            int cc = idx & 63, k2 = idx >> 6, kg2 = kt + k2, c = colBase + cc;
            Bs[k2 * 64 + cc] = (kg2 < 128) ? rki[n * 16384 + kg2 * 128 + c]
                                           : rks[n * 16384 + (kg2 - 128) * 128 + c];
        }
        __syncthreads();
#pragma unroll
        for (int k = 0; k < 16; k++) {
            float4 a = *(const float4*)&As[k * 64 + r0];
            float4 bb = *(const float4*)&Bs[k * 64 + c0];
            float av[4] = {a.x, a.y, a.z, a.w}, bv[4] = {bb.x, bb.y, bb.z, bb.w};
#pragma unroll
            for (int i = 0; i < 4; i++)
#pragma unroll
                for (int j = 0; j < 4; j++) acc[i][j] += av[i] * bv[j];
        }
        __syncthreads();
    }
#pragma unroll
    for (int i = 0; i < 4; i++)
#pragma unroll
        for (int j = 0; j < 4; j++)
            d_aggin[n * 131072 + (rowBase + r0 + i) * 128 + colBase + c0 + j] = acc[i][j];
}

// ---------- K6: sub LN + expansion -> E ----------
__global__ __launch_bounds__(128) void k_subexpand(const float* __restrict__ lg,
                                                   const float* __restrict__ lb) {
    __shared__ float sh[128];
    int bx = blockIdx.x, t = threadIdx.x;
    int n = bx >> 10;
    float v = d_aggin[bx * 128 + t];
    float S = red128(v, sh), Q = red128(v * v, sh);
    float mean = S * (1.f / 128.f);
    float rstd = rsqrtf(Q * (1.f / 128.f) - mean * mean + 1e-3f);
    float xn = (v - mean) * rstd * lg[n * 128 + t] + lb[n * 128 + t];
    float e[9];
    kan_expand(xn, e);
    size_t base = (size_t)bx * 1152 + t * 9;
#pragma unroll
    for (int j = 0; j < 9; j++) d_subE[base + j] = e[j];
}

// ---------- K7: pack sub weights interleaved [f*9+j][o] ----------
__global__ void k_packW(const float* __restrict__ bw, const float* __restrict__ sw) {
    int idx = blockIdx.x * 256 + threadIdx.x;
    if (idx >= 3 * 1152 * 128) return;
    int n = idx / 147456, rem = idx - n * 147456;
    int k = rem >> 7, o = rem & 127;
    int f = k / 9, j = k - f * 9;
    d_subW[idx] = (j == 0) ? bw[n * 16384 + f * 128 + o]
                           : sw[n * 131072 + (f * 8 + j - 1) * 128 + o];
}

// ---------- K8: sub GEMM + epilogue (scale, new states, agg) ----------
__global__ __launch_bounds__(256) void k_subgemm(const float* __restrict__ ss,
                                                 const float* __restrict__ subk,
                                                 float* __restrict__ out_ss) {
    __shared__ float As[16 * 64], Bs[16 * 64];
    int tid = threadIdx.x, n = blockIdx.z;
    int rowBase = blockIdx.y * 64, colBase = blockIdx.x * 64;
    int r0 = (tid >> 4) * 4, c0 = (tid & 15) * 4;
    float acc[4][4] = {};
    for (int kt = 0; kt < 1152; kt += 16) {
        for (int idx = tid; idx < 1024; idx += 256) {
            int kk = idx & 15, m = idx >> 4, b = rowBase + m;
            As[kk * 64 + m] = d_subE[((size_t)(n * 1024 + b)) * 1152 + kt + kk];
            int cc = idx & 63, k2 = idx >> 6, c = colBase + cc;
            Bs[k2 * 64 + cc] = d_subW[n * 147456 + (kt + k2) * 128 + c];
        }
        __syncthreads();
#pragma unroll
        for (int k = 0; k < 16; k++) {
            float4 a = *(const float4*)&As[k * 64 + r0];
            float4 bb = *(const float4*)&Bs[k * 64 + c0];
            float av[4] = {a.x, a.y, a.z, a.w}, bv[4] = {bb.x, bb.y, bb.z, bb.w};
#pragma unroll
            for (int i = 0; i < 4; i++)
#pragma unroll
                for (int j = 0; j < 4; j++) acc[i][j] += av[i] * bv[j];
        }
        __syncthreads();
    }
#pragma unroll
    for (int i = 0; i < 4; i++)
#pragma unroll
        for (int j = 0; j < 4; j++) {
            int b = rowBase + r0 + i, o = colBase + c0 + j;
            float v = acc[i][j] * d_sigw[b * 3 + n];
            d_agg[b * 384 + n * 128 + o] = v;
            out_ss[n * 131072 + b * 128 + o] =
                subk[n * 256 + o] * v + ss[n * 131072 + b * 128 + o] * subk[n * 256 + 128 + o];
        }
}

// ---------- K9: x_o GEMM + final c, h ----------
__global__ __launch_bounds__(256) void k_final(const float* __restrict__ aw, const float* __restrict__ ab,
                                               const float* __restrict__ c0p, float* __restrict__ out) {
    __shared__ float As[16 * 64], Bs[16 * 64];
    int tid = threadIdx.x;
    int rowBase = blockIdx.y * 64, colBase = blockIdx.x * 64;
    int r0 = (tid >> 4) * 4, cc0 = (tid & 15) * 4;
    float acc[4][4] = {};
    for (int kt = 0; kt < 384; kt += 16) {
        for (int idx = tid; idx < 1024; idx += 256) {
            int kk = idx & 15, m = idx >> 4;
            As[kk * 64 + m] = d_agg[(rowBase + m) * 384 + kt + kk];
            int cc = idx & 63, k2 = idx >> 6;
            Bs[k2 * 64 + cc] = aw[(kt + k2) * 512 + colBase + cc];
        }
        __syncthreads();
#pragma unroll
        for (int k = 0; k < 16; k++) {
            float4 a = *(const float4*)&As[k * 64 + r0];
            float4 bb = *(const float4*)&Bs[k * 64 + cc0];
            float av[4] = {a.x, a.y, a.z, a.w}, bv[4] = {bb.x, bb.y, bb.z, bb.w};
#pragma unroll
            for (int i = 0; i < 4; i++)
#pragma unroll
                for (int j = 0; j < 4; j++) acc[i][j] += av[i] * bv[j];
        }
        __syncthreads();
    }
#pragma unroll
    for (int i = 0; i < 4; i++)
#pragma unroll
        for (int j = 0; j < 4; j++) {
            int b = rowBase + r0 + i, c = colBase + cc0 + j;
            float xo = sigm(acc[i][j] + ab[c]);
            float zi = d_z[b * 1536 + c];
            float zf = d_z[b * 1536 + 512 + c];
            float zc = d_z[b * 1536 + 1024 + c];
            float cv = zf * c0p[b * 512 + c] + zi * zc;
            out[b * 512 + c] = xo * tanhf(cv);
            out[B_ * U_ + b * 512 + c] = cv;
        }
}

// ---------- launch ----------
extern "C" void kernel_launch(void* const* d_in, const int* in_sizes, int n_in,
                              void* d_out, int out_size) {
    const float* inputs   = (const float*)d_in[0];
    const float* h0       = (const float*)d_in[1];
    const float* c0       = (const float*)d_in[2];
    const float* sub_st   = (const float*)d_in[3];
    const float* kern     = (const float*)d_in[4];
    const float* rkern    = (const float*)d_in[5];
    const float* bias     = (const float*)d_in[6];
    const float* sub_k    = (const float*)d_in[7];
    const float* sub_rki  = (const float*)d_in[8];
    const float* sub_rks  = (const float*)d_in[9];
    const float* agg_w    = (const float*)d_in[10];
    const float* agg_b    = (const float*)d_in[11];
    const float* sub_lng  = (const float*)d_in[12];
    const float* sub_lnb  = (const float*)d_in[13];
    const float* sub_bw   = (const float*)d_in[14];
    const float* sub_sw   = (const float*)d_in[15];
    const float* g_skw    = (const float*)d_in[16];
    const float* g_skb    = (const float*)d_in[17];
    const float* k1_lng   = (const float*)d_in[18];
    const float* k1_lnb   = (const float*)d_in[19];
    const float* k1_base  = (const float*)d_in[20];
    const float* k1_spl   = (const float*)d_in[21];
    const float* k2_lng   = (const float*)d_in[22];
    const float* k2_lnb   = (const float*)d_in[23];
    const float* k2_base  = (const float*)d_in[24];
    const float* k2_spl   = (const float*)d_in[25];
    const float* gw       = (const float*)d_in[26];
    const float* gb       = (const float*)d_in[27];
    const float* sw       = (const float*)d_in[28];
    const float* sb       = (const float*)d_in[29];
    const float* lg       = (const float*)d_in[30];
    const float* lb       = (const float*)d_in[31];
    float* out = (float*)d_out;

    static bool attr_set = false;
    if (!attr_set) {
        cudaFuncSetAttribute(k_kan1, cudaFuncAttributeMaxDynamicSharedMemorySize, 70144);
        attr_set = true;
    }

    k_stats<<<B_, 128>>>(inputs, g_skw, g_skb);
    k_kan1<<<dim3(8, 16), 256, 70144>>>(inputs, k1_lng, k1_lnb, k1_base, k1_spl);
    k_head<<<B_, 128>>>(k2_lng, k2_lnb, k2_base, k2_spl, gw, gb, sw, sb, lg, lb);
    k_z<<<dim3(24, 16), 256>>>(inputs, h0, kern, rkern, bias);
    k_aggin<<<dim3(2, 16, 3), 256>>>(inputs, sub_st, sub_rki, sub_rks);
    k_subexpand<<<3 * B_, 128>>>(sub_lng, sub_lnb);
    k_packW<<<(3 * 1152 * 128 + 255) / 256, 256>>>(sub_bw, sub_sw);
    k_subgemm<<<dim3(2, 16, 3), 256>>>(sub_st, sub_k, out + 2 * B_ * U_);
    k_final<<<dim3(8, 16), 256>>>(agg_w, agg_b, c0, out);
}

// round 5
// speedup vs baseline: 1.0001x; 1.0001x over previous
#include <cuda_runtime.h>

#define DEV __device__ __forceinline__
typedef unsigned long long ull;

#define B_ 1024
#define U_ 512
#define SIGD 16512

// ---------- scratch ----------
__device__ float d_mu[B_];
__device__ float d_rstd[B_];
__device__ float d_skip[B_ * 3];
__device__ float d_sigw[B_ * 3];
__device__ __align__(16) float d_z[B_ * 1536];
__device__ __align__(16) float d_h1[B_ * U_];
__device__ __align__(16) float d_aggin[3 * B_ * 128];
__device__ __align__(16) float d_subE[3 * B_ * 1152];
__device__ __align__(16) float d_subW[3 * 1152 * 128];
__device__ __align__(16) float d_agg[B_ * 384];

// ---------- helpers ----------
DEV float sigm(float x) { return 1.f / (1.f + __expf(-x)); }

DEV ull dup2(float x) { ull r; asm("mov.b64 %0,{%1,%1};" : "=l"(r) : "f"(x)); return r; }
DEV void fma2(ull& d, ull a, ull b) { asm("fma.rn.f32x2 %0,%1,%2,%0;" : "+l"(d) : "l"(a), "l"(b)); }
DEV float2 unpk(ull p) { float lo, hi; asm("mov.b64 {%0,%1},%2;" : "=f"(lo), "=f"(hi) : "l"(p)); return make_float2(lo, hi); }

// silu + 8 cubic B-spline bases; knots -2.2 + 0.4k
DEV void kan_expand(float xn, float e[9]) {
    e[0] = xn * sigm(xn);
#pragma unroll
    for (int j = 1; j < 9; j++) e[j] = 0.f;
    float tp = (xn + 2.2f) * 2.5f;
    float tf = floorf(tp);
    if (tf >= 0.f && tf <= 10.f) {
        int t = (int)tf;
        float u = tp - tf, u2 = u * u, u3 = u2 * u, omu = 1.f - u;
        float v0 = omu * omu * omu * (1.f / 6.f);
        float v1 = (3.f * u3 - 6.f * u2 + 4.f) * (1.f / 6.f);
        float v2 = (-3.f * u3 + 3.f * u2 + 3.f * u + 1.f) * (1.f / 6.f);
        float v3 = u3 * (1.f / 6.f);
        if (t >= 3)           e[t - 2] = v0;
        if (t >= 2 && t <= 9) e[t - 1] = v1;
        if (t >= 1 && t <= 8) e[t]     = v2;
        if (t <= 7)           e[t + 1] = v3;
    }
}

DEV float red128(float v, float* sh) {
    int t = threadIdx.x;
    sh[t] = v; __syncthreads();
#pragma unroll
    for (int s = 64; s > 0; s >>= 1) { if (t < s) sh[t] += sh[t + s]; __syncthreads(); }
    float r = sh[0]; __syncthreads();
    return r;
}

// ---------- K1: sig LN stats (closed form) + skip ----------
__global__ __launch_bounds__(128) void k_stats(const float* __restrict__ x,
                                               const float* __restrict__ skw,
                                               const float* __restrict__ skb) {
    __shared__ float xs[128], sh[128];
    int b = blockIdx.x, t = threadIdx.x;
    float xv = x[b * 128 + t];
    xs[t] = xv; __syncthreads();
    float S = red128(xv, sh);
    float Q = red128(xv * xv, sh);
    if (t == 0) {
        float mean = (S + 0.5f * S * S) / (float)SIGD;
        float m2 = (Q + 0.25f * Q * Q) / (float)SIGD;
        d_mu[b] = mean;
        d_rstd[b] = rsqrtf(m2 - mean * mean + 1e-3f);
    }
    float a0 = 0.f, a1 = 0.f, a2 = 0.f;
    for (int i = t; i < SIGD; i += 128) {
        float sv = (i < 128) ? xs[i] : 0.5f * xs[(i - 128) >> 7] * xs[(i - 128) & 127];
        a0 += sv * skw[i * 3 + 0];
        a1 += sv * skw[i * 3 + 1];
        a2 += sv * skw[i * 3 + 2];
    }
    a0 = red128(a0, sh); a1 = red128(a1, sh); a2 = red128(a2, sh);
    if (t == 0) {
        d_skip[b * 3 + 0] = a0 + skb[0];
        d_skip[b * 3 + 1] = a1 + skb[1];
        d_skip[b * 3 + 2] = a2 + skb[2];
    }
}

// ---------- K2: the big KAN GEMM (sig -> h1) ----------
// grid (8,16): 64 cols x 64 rows per block. K = 16512 features * 9.
__global__ __launch_bounds__(256) void k_kan1(const float* __restrict__ x,
                                              const float* __restrict__ lng,
                                              const float* __restrict__ lnb,
                                              const float* __restrict__ wb,
                                              const float* __restrict__ ws) {
    extern __shared__ float sm[];
    float* xs = sm;                 // 64*128
    float* As = sm + 8192;          // 72*64
    float* Bs = sm + 8192 + 4608;   // 72*64
    float* mus = sm + 8192 + 9216;  // 64
    float* rss = mus + 64;          // 64
    int tid = threadIdx.x;
    int rowBase = blockIdx.y * 64, colBase = blockIdx.x * 64;

    for (int idx = tid; idx < 8192; idx += 256)
        xs[idx] = x[(rowBase + (idx >> 7)) * 128 + (idx & 127)];
    if (tid < 64) { mus[tid] = d_mu[rowBase + tid]; rss[tid] = d_rstd[rowBase + tid]; }
    __syncthreads();

    int r0 = (tid >> 4) * 4, c0 = (tid & 15) * 4;
    ull acc[2][4] = {};
    float4 w[5];

#define LOADW(CH) {                                                          \
    int f0_ = (CH) * 8;                                                      \
    _Pragma("unroll")                                                        \
    for (int m = 0; m < 5; m++) {                                            \
        int idx = tid + m * 256;                                             \
        if (idx < 1152) {                                                    \
            int kk = idx >> 4, c4 = (idx & 15) << 2;                         \
            int fi = kk / 9, j = kk - fi * 9;                                \
            size_t i = (size_t)(f0_ + fi);                                   \
            const float* p = (j == 0) ? wb + i * 512 + colBase + c4          \
                                      : ws + (i * 8 + (j - 1)) * 512 + colBase + c4; \
            w[m] = *(const float4*)p;                                        \
        }                                                                    \
    } }

    LOADW(0)
    for (int ch = 0; ch < 2064; ch++) {
#pragma unroll
        for (int m = 0; m < 5; m++) {
            int idx = tid + m * 256;
            if (idx < 1152) {
                int kk = idx >> 4, c4 = (idx & 15) << 2;
                *(float4*)&Bs[kk * 64 + c4] = w[m];
            }
        }
#pragma unroll
        for (int t2 = tid; t2 < 512; t2 += 256) {
            int f = t2 >> 6, b = t2 & 63;
            int i = ch * 8 + f;
            float val = (i < 128) ? xs[b * 128 + i]
                                  : 0.5f * xs[b * 128 + ((i - 128) >> 7)] * xs[b * 128 + ((i - 128) & 127)];
            float xn = (val - mus[b]) * rss[b] * __ldg(lng + i) + __ldg(lnb + i);
            float e[9];
            kan_expand(xn, e);
#pragma unroll
            for (int j = 0; j < 9; j++) As[(f * 9 + j) * 64 + b] = e[j];
        }
        if (ch + 1 < 2064) LOADW(ch + 1)
        __syncthreads();
#pragma unroll 8
        for (int k = 0; k < 72; k++) {
            const float* ap = &As[k * 64 + r0];
            ull a0 = *(const ull*)ap;
            ull a1 = *(const ull*)(ap + 2);
            float4 b4 = *(const float4*)&Bs[k * 64 + c0];
            ull b0 = dup2(b4.x), b1 = dup2(b4.y), b2 = dup2(b4.z), b3 = dup2(b4.w);
            fma2(acc[0][0], a0, b0); fma2(acc[0][1], a0, b1);
            fma2(acc[0][2], a0, b2); fma2(acc[0][3], a0, b3);
            fma2(acc[1][0], a1, b0); fma2(acc[1][1], a1, b1);
            fma2(acc[1][2], a1, b2); fma2(acc[1][3], a1, b3);
        }
        __syncthreads();
    }
#undef LOADW
#pragma unroll
    for (int p = 0; p < 2; p++)
#pragma unroll
        for (int c = 0; c < 4; c++) {
            float2 v = unpk(acc[p][c]);
            int row = rowBase + r0 + 2 * p, col = colBase + c0 + c;
            d_h1[row * 512 + col] = v.x;
            d_h1[(row + 1) * 512 + col] = v.y;
        }
}

// ---------- K3: head — kan2 (512->3), GLU, LN, softmax -> sig weights ----------
__global__ __launch_bounds__(128) void k_head(const float* __restrict__ g2g,
                                              const float* __restrict__ g2b,
                                              const float* __restrict__ k2base,
                                              const float* __restrict__ k2spl,
                                              const float* __restrict__ gw, const float* __restrict__ gb,
                                              const float* __restrict__ sw, const float* __restrict__ sb,
                                              const float* __restrict__ lg, const float* __restrict__ lb) {
    __shared__ float sh[128];
    int b = blockIdx.x, t = threadIdx.x;
    float v[4], S = 0.f, Q = 0.f;
#pragma unroll
    for (int m = 0; m < 4; m++) {
        v[m] = d_h1[b * 512 + t + 128 * m];
        S += v[m]; Q += v[m] * v[m];
    }
    S = red128(S, sh); Q = red128(Q, sh);
    float mean = S / 512.f;
    float rstd = rsqrtf(Q / 512.f - mean * mean + 1e-3f);
    float a0 = 0.f, a1 = 0.f, a2 = 0.f;
#pragma unroll
    for (int m = 0; m < 4; m++) {
        int i = t + 128 * m;
        float xn = (v[m] - mean) * rstd * g2g[i] + g2b[i];
        float e[9];
        kan_expand(xn, e);
        a0 += e[0] * k2base[i * 3 + 0];
        a1 += e[0] * k2base[i * 3 + 1];
        a2 += e[0] * k2base[i * 3 + 2];
#pragma unroll
        for (int j = 0; j < 8; j++) {
            const float* sp = k2spl + (size_t)(i * 8 + j) * 3;
            a0 += e[1 + j] * sp[0];
            a1 += e[1 + j] * sp[1];
            a2 += e[1 + j] * sp[2];
        }
    }
    a0 = red128(a0, sh); a1 = red128(a1, sh); a2 = red128(a2, sh);
    if (t == 0) {
        float h2[3] = {a0, a1, a2};
        float y[3];
#pragma unroll
        for (int o = 0; o < 3; o++) {
            float g1 = gb[o], s1 = sb[o];
#pragma unroll
            for (int p = 0; p < 3; p++) { g1 += h2[p] * gw[p * 3 + o]; s1 += h2[p] * sw[p * 3 + o]; }
            y[o] = d_skip[b * 3 + o] + g1 * sigm(s1);
        }
        float m = (y[0] + y[1] + y[2]) * (1.f / 3.f);
        float var = ((y[0] - m) * (y[0] - m) + (y[1] - m) * (y[1] - m) + (y[2] - m) * (y[2] - m)) * (1.f / 3.f);
        float rs = rsqrtf(var + 1e-3f);
        float yn[3], mx = -1e30f;
#pragma unroll
        for (int o = 0; o < 3; o++) { yn[o] = (y[o] - m) * rs * lg[o] + lb[o]; mx = fmaxf(mx, yn[o]); }
        float e0 = __expf(yn[0] - mx), e1 = __expf(yn[1] - mx), e2 = __expf(yn[2] - mx);
        float inv = 1.f / (e0 + e1 + e2);
        d_sigw[b * 3 + 0] = e0 * inv;
        d_sigw[b * 3 + 1] = e1 * inv;
        d_sigw[b * 3 + 2] = e2 * inv;
    }
}

// ---------- K4: LSTM gates z = sigmoid([x|h0]@[W;R] + bias) ----------
__global__ __launch_bounds__(256) void k_z(const float* __restrict__ x, const float* __restrict__ h0,
                                           const float* __restrict__ W1, const float* __restrict__ W2,
                                           const float* __restrict__ bias) {
    __shared__ float As[16 * 64], Bs[16 * 64];
    int tid = threadIdx.x;
    int rowBase = blockIdx.y * 64, colBase = blockIdx.x * 64;
    int r0 = (tid >> 4) * 4, c0 = (tid & 15) * 4;
    float acc[4][4] = {};
    for (int kt = 0; kt < 640; kt += 16) {
        for (int idx = tid; idx < 1024; idx += 256) {
            int kk = idx & 15, m = idx >> 4, kg = kt + kk, b = rowBase + m;
            As[kk * 64 + m] = (kg < 128) ? x[b * 128 + kg] : h0[b * 512 + kg - 128];
            int cc = idx & 63, k2 = idx >> 6, kg2 = kt + k2, c = colBase + cc;
            Bs[k2 * 64 + cc] = (kg2 < 128) ? W1[kg2 * 1536 + c] : W2[(size_t)(kg2 - 128) * 1536 + c];
        }
        __syncthreads();
#pragma unroll
        for (int k = 0; k < 16; k++) {
            float4 a = *(const float4*)&As[k * 64 + r0];
            float4 bb = *(const float4*)&Bs[k * 64 + c0];
            float av[4] = {a.x, a.y, a.z, a.w}, bv[4] = {bb.x, bb.y, bb.z, bb.w};
#pragma unroll
            for (int i = 0; i < 4; i++)
#pragma unroll
                for (int j = 0; j < 4; j++) acc[i][j] += av[i] * bv[j];
        }
        __syncthreads();
    }
#pragma unroll
    for (int i = 0; i < 4; i++)
#pragma unroll
        for (int j = 0; j < 4; j++) {
            int b = rowBase + r0 + i, c = colBase + c0 + j;
            d_z[b * 1536 + c] = sigm(acc[i][j] + bias[c]);
        }
}

// ---------- K5: agg_in = x@rk_in[n] + sub_states[n]@rk_st[n] ----------
__global__ __launch_bounds__(256) void k_aggin(const float* __restrict__ x, const float* __restrict__ ss,
                                               const float* __restrict__ rki, const float* __restrict__ rks) {
    __shared__ float As[16 * 64], Bs[16 * 64];
    int tid = threadIdx.x, n = blockIdx.z;
    int rowBase = blockIdx.y * 64, colBase = blockIdx.x * 64;
    int r0 = (tid >> 4) * 4, c0 = (tid & 15) * 4;
    float acc[4][4] = {};
    for (int kt = 0; kt < 256; kt += 16) {
        for (int idx = tid; idx < 1024; idx += 256) {
            int kk = idx & 15, m = idx >> 4, kg = kt + kk, b = rowBase + m;
            As[kk * 64 + m] = (kg < 128) ? x[b * 128 + kg] : ss[n * 131072 + b * 128 + kg - 128];
            int cc = idx & 63, k2 = idx >> 6, kg2 = kt + k2, c = colBase + cc;
            Bs[k2 * 64 + cc] = (kg2 < 128) ? rki[n * 16384 + kg2 * 128 + c]
                                           : rks[n * 16384 + (kg2 - 128) * 128 + c];
        }
        __syncthreads();
#pragma unroll
        for (int k = 0; k < 16; k++) {
            float4 a = *(const float4*)&As[k * 64 + r0];
            float4 bb = *(const float4*)&Bs[k * 64 + c0];
            float av[4] = {a.x, a.y, a.z, a.w}, bv[4] = {bb.x, bb.y, bb.z, bb.w};
#pragma unroll
            for (int i = 0; i < 4; i++)
#pragma unroll
                for (int j = 0; j < 4; j++) acc[i][j] += av[i] * bv[j];
        }
        __syncthreads();
    }
#pragma unroll
    for (int i = 0; i < 4; i++)
#pragma unroll
        for (int j = 0; j < 4; j++)
            d_aggin[n * 131072 + (rowBase + r0 + i) * 128 + colBase + c0 + j] = acc[i][j];
}

// ---------- K6: sub LN + expansion -> E ----------
__global__ __launch_bounds__(128) void k_subexpand(const float* __restrict__ lg,
                                                   const float* __restrict__ lb) {
    __shared__ float sh[128];
    int bx = blockIdx.x, t = threadIdx.x;
    int n = bx >> 10;
    float v = d_aggin[bx * 128 + t];
    float S = red128(v, sh), Q = red128(v * v, sh);
    float mean = S * (1.f / 128.f);
    float rstd = rsqrtf(Q * (1.f / 128.f) - mean * mean + 1e-3f);
    float xn = (v - mean) * rstd * lg[n * 128 + t] + lb[n * 128 + t];
    float e[9];
    kan_expand(xn, e);
    size_t base = (size_t)bx * 1152 + t * 9;
#pragma unroll
    for (int j = 0; j < 9; j++) d_subE[base + j] = e[j];
}

// ---------- K7: pack sub weights interleaved [f*9+j][o] ----------
__global__ void k_packW(const float* __restrict__ bw, const float* __restrict__ sw) {
    int idx = blockIdx.x * 256 + threadIdx.x;
    if (idx >= 3 * 1152 * 128) return;
    int n = idx / 147456, rem = idx - n * 147456;
    int k = rem >> 7, o = rem & 127;
    int f = k / 9, j = k - f * 9;
    d_subW[idx] = (j == 0) ? bw[n * 16384 + f * 128 + o]
                           : sw[n * 131072 + (f * 8 + j - 1) * 128 + o];
}

// ---------- K8: sub GEMM + epilogue (scale, new states, agg) ----------
__global__ __launch_bounds__(256) void k_subgemm(const float* __restrict__ ss,
                                                 const float* __restrict__ subk,
                                                 float* __restrict__ out_ss) {
    __shared__ float As[16 * 64], Bs[16 * 64];
    int tid = threadIdx.x, n = blockIdx.z;
    int rowBase = blockIdx.y * 64, colBase = blockIdx.x * 64;
    int r0 = (tid >> 4) * 4, c0 = (tid & 15) * 4;
    float acc[4][4] = {};
    for (int kt = 0; kt < 1152; kt += 16) {
        for (int idx = tid; idx < 1024; idx += 256) {
            int kk = idx & 15, m = idx >> 4, b = rowBase + m;
            As[kk * 64 + m] = d_subE[((size_t)(n * 1024 + b)) * 1152 + kt + kk];
            int cc = idx & 63, k2 = idx >> 6, c = colBase + cc;
            Bs[k2 * 64 + cc] = d_subW[n * 147456 + (kt + k2) * 128 + c];
        }
        __syncthreads();
#pragma unroll
        for (int k = 0; k < 16; k++) {
            float4 a = *(const float4*)&As[k * 64 + r0];
            float4 bb = *(const float4*)&Bs[k * 64 + c0];
            float av[4] = {a.x, a.y, a.z, a.w}, bv[4] = {bb.x, bb.y, bb.z, bb.w};
#pragma unroll
            for (int i = 0; i < 4; i++)
#pragma unroll
                for (int j = 0; j < 4; j++) acc[i][j] += av[i] * bv[j];
        }
        __syncthreads();
    }
#pragma unroll
    for (int i = 0; i < 4; i++)
#pragma unroll
        for (int j = 0; j < 4; j++) {
            int b = rowBase + r0 + i, o = colBase + c0 + j;
            float v = acc[i][j] * d_sigw[b * 3 + n];
            d_agg[b * 384 + n * 128 + o] = v;
            out_ss[n * 131072 + b * 128 + o] =
                subk[n * 256 + o] * v + ss[n * 131072 + b * 128 + o] * subk[n * 256 + 128 + o];
        }
}

// ---------- K9: x_o GEMM + final c, h ----------
__global__ __launch_bounds__(256) void k_final(const float* __restrict__ aw, const float* __restrict__ ab,
                                               const float* __restrict__ c0p, float* __restrict__ out) {
    __shared__ float As[16 * 64], Bs[16 * 64];
    int tid = threadIdx.x;
    int rowBase = blockIdx.y * 64, colBase = blockIdx.x * 64;
    int r0 = (tid >> 4) * 4, cc0 = (tid & 15) * 4;
    float acc[4][4] = {};
    for (int kt = 0; kt < 384; kt += 16) {
        for (int idx = tid; idx < 1024; idx += 256) {
            int kk = idx & 15, m = idx >> 4;
            As[kk * 64 + m] = d_agg[(rowBase + m) * 384 + kt + kk];
            int cc = idx & 63, k2 = idx >> 6;
            Bs[k2 * 64 + cc] = aw[(kt + k2) * 512 + colBase + cc];
        }
        __syncthreads();
#pragma unroll
        for (int k = 0; k < 16; k++) {
            float4 a = *(const float4*)&As[k * 64 + r0];
            float4 bb = *(const float4*)&Bs[k * 64 + cc0];
            float av[4] = {a.x, a.y, a.z, a.w}, bv[4] = {bb.x, bb.y, bb.z, bb.w};
#pragma unroll
            for (int i = 0; i < 4; i++)
#pragma unroll
                for (int j = 0; j < 4; j++) acc[i][j] += av[i] * bv[j];
        }
        __syncthreads();
    }
#pragma unroll
    for (int i = 0; i < 4; i++)
#pragma unroll
        for (int j = 0; j < 4; j++) {
            int b = rowBase + r0 + i, c = colBase + cc0 + j;
            float xo = sigm(acc[i][j] + ab[c]);
            float zi = d_z[b * 1536 + c];
            float zf = d_z[b * 1536 + 512 + c];
            float zc = d_z[b * 1536 + 1024 + c];
            float cv = zf * c0p[b * 512 + c] + zi * zc;
            out[b * 512 + c] = xo * tanhf(cv);
            out[B_ * U_ + b * 512 + c] = cv;
        }
}

// ---------- launch ----------
extern "C" void kernel_launch(void* const* d_in, const int* in_sizes, int n_in,
                              void* d_out, int out_size) {
    const float* inputs   = (const float*)d_in[0];
    const float* h0       = (const float*)d_in[1];
    const float* c0       = (const float*)d_in[2];
    const float* sub_st   = (const float*)d_in[3];
    const float* kern     = (const float*)d_in[4];
    const float* rkern    = (const float*)d_in[5];
    const float* bias     = (const float*)d_in[6];
    const float* sub_k    = (const float*)d_in[7];
    const float* sub_rki  = (const float*)d_in[8];
    const float* sub_rks  = (const float*)d_in[9];
    const float* agg_w    = (const float*)d_in[10];
    const float* agg_b    = (const float*)d_in[11];
    const float* sub_lng  = (const float*)d_in[12];
    const float* sub_lnb  = (const float*)d_in[13];
    const float* sub_bw   = (const float*)d_in[14];
    const float* sub_sw   = (const float*)d_in[15];
    const float* g_skw    = (const float*)d_in[16];
    const float* g_skb    = (const float*)d_in[17];
    const float* k1_lng   = (const float*)d_in[18];
    const float* k1_lnb   = (const float*)d_in[19];
    const float* k1_base  = (const float*)d_in[20];
    const float* k1_spl   = (const float*)d_in[21];
    const float* k2_lng   = (const float*)d_in[22];
    const float* k2_lnb   = (const float*)d_in[23];
    const float* k2_base  = (const float*)d_in[24];
    const float* k2_spl   = (const float*)d_in[25];
    const float* gw       = (const float*)d_in[26];
    const float* gb       = (const float*)d_in[27];
    const float* sw       = (const float*)d_in[28];
    const float* sb       = (const float*)d_in[29];
    const float* lg       = (const float*)d_in[30];
    const float* lb       = (const float*)d_in[31];
    float* out = (float*)d_out;

    static bool attr_set = false;
    if (!attr_set) {
        cudaFuncSetAttribute(k_kan1, cudaFuncAttributeMaxDynamicSharedMemorySize, 70144);
        attr_set = true;
    }

    k_stats<<<B_, 128>>>(inputs, g_skw, g_skb);
    k_kan1<<<dim3(8, 16), 256, 70144>>>(inputs, k1_lng, k1_lnb, k1_base, k1_spl);
    k_head<<<B_, 128>>>(k2_lng, k2_lnb, k2_base, k2_spl, gw, gb, sw, sb, lg, lb);
    k_z<<<dim3(24, 16), 256>>>(inputs, h0, kern, rkern, bias);
    k_aggin<<<dim3(2, 16, 3), 256>>>(inputs, sub_st, sub_rki, sub_rks);
    k_subexpand<<<3 * B_, 128>>>(sub_lng, sub_lnb);
    k_packW<<<(3 * 1152 * 128 + 255) / 256, 256>>>(sub_bw, sub_sw);
    k_subgemm<<<dim3(2, 16, 3), 256>>>(sub_st, sub_k, out + 2 * B_ * U_);
    k_final<<<dim3(8, 16), 256>>>(agg_w, agg_b, c0, out);
}

// round 7
// speedup vs baseline: 2.1693x; 2.1691x over previous
#include <cuda_runtime.h>
#include <cuda_bf16.h>
#include <stdint.h>

#define DEV __device__ __forceinline__
typedef unsigned long long ull;

#define B_ 1024
#define U_ 512
#define SIGD 16512

// ---------- scratch ----------
__device__ float d_mu[B_];
__device__ float d_rstd[B_];
__device__ float d_skip[B_ * 3];
__device__ float d_sigw[B_ * 3];
__device__ __align__(16) float d_z[B_ * 1536];
__device__ __align__(16) float d_h1[B_ * U_];
__device__ __align__(16) float d_aggin[3 * B_ * 128];
__device__ __align__(16) float d_subE[3 * B_ * 1152];
__device__ __align__(16) float d_subW[3 * 1152 * 128];
__device__ __align__(16) float d_agg[B_ * 384];
__device__ __align__(16) float d_part[4 * B_ * U_];

// ---------- helpers ----------
DEV float sigm(float x) { return 1.f / (1.f + __expf(-x)); }
DEV uint32_t s2u(const void* p) {
    uint32_t a;
    asm("{ .reg .u64 t; cvta.to.shared.u64 t,%1; cvt.u32.u64 %0,t; }" : "=r"(a) : "l"(p));
    return a;
}
DEV void ldsm4(uint32_t r[4], uint32_t addr) {
    asm volatile("ldmatrix.sync.aligned.m8n8.x4.shared.b16 {%0,%1,%2,%3},[%4];"
                 : "=r"(r[0]), "=r"(r[1]), "=r"(r[2]), "=r"(r[3]) : "r"(addr));
}
DEV void ldsm4t(uint32_t r[4], uint32_t addr) {
    asm volatile("ldmatrix.sync.aligned.m8n8.x4.trans.shared.b16 {%0,%1,%2,%3},[%4];"
                 : "=r"(r[0]), "=r"(r[1]), "=r"(r[2]), "=r"(r[3]) : "r"(addr));
}
DEV void mma_bf16(float acc[4], const uint32_t a[4], const uint32_t b[2]) {
    asm volatile(
        "mma.sync.aligned.m16n8k16.row.col.f32.bf16.bf16.f32 "
        "{%0,%1,%2,%3},{%4,%5,%6,%7},{%8,%9},{%0,%1,%2,%3};"
        : "+f"(acc[0]), "+f"(acc[1]), "+f"(acc[2]), "+f"(acc[3])
        : "r"(a[0]), "r"(a[1]), "r"(a[2]), "r"(a[3]), "r"(b[0]), "r"(b[1]));
}

DEV void kan_expand(float xn, float e[9]) {
    e[0] = xn * sigm(xn);
#pragma unroll
    for (int j = 1; j < 9; j++) e[j] = 0.f;
    float tp = (xn + 2.2f) * 2.5f;
    float tf = floorf(tp);
    if (tf >= 0.f && tf <= 10.f) {
        int t = (int)tf;
        float u = tp - tf, u2 = u * u, u3 = u2 * u, omu = 1.f - u;
        float v0 = omu * omu * omu * (1.f / 6.f);
        float v1 = (3.f * u3 - 6.f * u2 + 4.f) * (1.f / 6.f);
        float v2 = (-3.f * u3 + 3.f * u2 + 3.f * u + 1.f) * (1.f / 6.f);
        float v3 = u3 * (1.f / 6.f);
        if (t >= 3)           e[t - 2] = v0;
        if (t >= 2 && t <= 9) e[t - 1] = v1;
        if (t >= 1 && t <= 8) e[t]     = v2;
        if (t <= 7)           e[t + 1] = v3;
    }
}

DEV float red128(float v, float* sh) {
    int t = threadIdx.x;
    sh[t] = v; __syncthreads();
#pragma unroll
    for (int s = 64; s > 0; s >>= 1) { if (t < s) sh[t] += sh[t + s]; __syncthreads(); }
    float r = sh[0]; __syncthreads();
    return r;
}

// ---------- K1: sig LN stats (closed form) + skip ----------
__global__ __launch_bounds__(128) void k_stats(const float* __restrict__ x,
                                               const float* __restrict__ skw,
                                               const float* __restrict__ skb) {
    __shared__ float xs[128], sh[128];
    int b = blockIdx.x, t = threadIdx.x;
    float xv = x[b * 128 + t];
    xs[t] = xv; __syncthreads();
    float S = red128(xv, sh);
    float Q = red128(xv * xv, sh);
    if (t == 0) {
        float mean = (S + 0.5f * S * S) / (float)SIGD;
        float m2 = (Q + 0.25f * Q * Q) / (float)SIGD;
        d_mu[b] = mean;
        d_rstd[b] = rsqrtf(m2 - mean * mean + 1e-3f);
    }
    float a0 = 0.f, a1 = 0.f, a2 = 0.f;
    for (int i = t; i < SIGD; i += 128) {
        float sv = (i < 128) ? xs[i] : 0.5f * xs[(i - 128) >> 7] * xs[(i - 128) & 127];
        a0 += sv * skw[i * 3 + 0];
        a1 += sv * skw[i * 3 + 1];
        a2 += sv * skw[i * 3 + 2];
    }
    a0 = red128(a0, sh); a1 = red128(a1, sh); a2 = red128(a2, sh);
    if (t == 0) {
        d_skip[b * 3 + 0] = a0 + skb[0];
        d_skip[b * 3 + 1] = a1 + skb[1];
        d_skip[b * 3 + 2] = a2 + skb[2];
    }
}

// ---------- K2: big KAN GEMM via mma.sync bf16 (2-limb, 3 products) ----------
// grid (ks=4, mg=8, ng=4) = 128 CTAs. Tile 128 rows x 128 cols, K-split 4128 feats.
// Chunks of 16 features = 144 k-units = 9 mma k-steps.
#define LDA 152
#define LDB 136
#define SM_MMA (2 * 128 * LDA * 2 + 2 * 144 * LDB * 2)   // 156160
__global__ __launch_bounds__(256) void k_mma(const float* __restrict__ x,
                                             const float* __restrict__ lng,
                                             const float* __restrict__ lnb,
                                             const float* __restrict__ wb,
                                             const float* __restrict__ ws) {
    extern __shared__ __nv_bfloat16 smb[];
    __nv_bfloat16* AH = smb;
    __nv_bfloat16* AL = AH + 128 * LDA;
    __nv_bfloat16* BH = AL + 128 * LDA;
    __nv_bfloat16* BL = BH + 144 * LDB;
    uint32_t aBH = s2u(AH), aBL = s2u(AL), bBH = s2u(BH), bBL = s2u(BL);

    int tid = threadIdx.x, lane = tid & 31, wid = tid >> 5;
    int ks = blockIdx.x, mg = blockIdx.y, ng = blockIdx.z;
    int rowBase = mg * 128, colBase = ng * 128;
    int warpRow = (wid & 3) * 32, warpCol = (wid >> 2) * 64;

    float acc[2][8][4];
#pragma unroll
    for (int mi = 0; mi < 2; mi++)
#pragma unroll
        for (int ni = 0; ni < 8; ni++)
#pragma unroll
            for (int q = 0; q < 4; q++) acc[mi][ni][q] = 0.f;

    int arow = lane & 15, acol = (lane >> 4) * 8;   // ldmatrix lane addressing
    int rsel = tid >> 5, n4 = (tid & 31) * 4;       // B loader mapping

    for (int ch = 0; ch < 258; ch++) {
        int f0 = ks * 4128 + ch * 16;
        // --- A: expand 16 feats x 128 rows into bf16 hi/lo ---
#pragma unroll
        for (int p = 0; p < 8; p++) {
            int task = tid + p * 256;
            int fl = task & 15, row = task >> 4;
            int fg = f0 + fl;
            const float* xr = x + (size_t)(rowBase + row) * 128;
            float val;
            if (fg < 128) val = __ldg(xr + fg);
            else {
                int q = fg - 128;
                val = 0.5f * __ldg(xr + (q >> 7)) * __ldg(xr + (q & 127));
            }
            float xn = (val - d_mu[rowBase + row]) * d_rstd[rowBase + row]
                     * __ldg(lng + fg) + __ldg(lnb + fg);
            float e[9];
            kan_expand(xn, e);
            int off = row * LDA + fl * 9;
#pragma unroll
            for (int j = 0; j < 9; j++) {
                __nv_bfloat16 h = __float2bfloat16(e[j]);
                AH[off + j] = h;
                AL[off + j] = __float2bfloat16(e[j] - __bfloat162float(h));
            }
        }
        // --- B: load 144 x 128 fp32, limb-split, store [k][n] ---
#pragma unroll
        for (int i = 0; i < 18; i++) {
            int kl = i * 8 + rsel;
            int kg = f0 * 9 + kl;
            int f = kg / 9, jj = kg - f * 9;
            const float* p = (jj == 0) ? wb + (size_t)f * 512
                                       : ws + ((size_t)f * 8 + (jj - 1)) * 512;
            float4 v = *(const float4*)(p + colBase + n4);
            __nv_bfloat16 h0 = __float2bfloat16(v.x), h1 = __float2bfloat16(v.y);
            __nv_bfloat16 h2 = __float2bfloat16(v.z), h3 = __float2bfloat16(v.w);
            uint2 hw;
            hw.x = ((uint32_t)__bfloat16_as_ushort(h1) << 16) | __bfloat16_as_ushort(h0);
            hw.y = ((uint32_t)__bfloat16_as_ushort(h3) << 16) | __bfloat16_as_ushort(h2);
            *(uint2*)&BH[kl * LDB + n4] = hw;
            __nv_bfloat16 l0 = __float2bfloat16(v.x - __bfloat162float(h0));
            __nv_bfloat16 l1 = __float2bfloat16(v.y - __bfloat162float(h1));
            __nv_bfloat16 l2 = __float2bfloat16(v.z - __bfloat162float(h2));
            __nv_bfloat16 l3 = __float2bfloat16(v.w - __bfloat162float(h3));
            uint2 lw;
            lw.x = ((uint32_t)__bfloat16_as_ushort(l1) << 16) | __bfloat16_as_ushort(l0);
            lw.y = ((uint32_t)__bfloat16_as_ushort(l3) << 16) | __bfloat16_as_ushort(l2);
            *(uint2*)&BL[kl * LDB + n4] = lw;
        }
        __syncthreads();
        // --- MMA: 9 k-steps of 16 ---
#pragma unroll 1
        for (int ks2 = 0; ks2 < 9; ks2++) {
            int k0 = ks2 * 16;
            uint32_t aH[2][4], aL[2][4];
#pragma unroll
            for (int mi = 0; mi < 2; mi++) {
                uint32_t off = (uint32_t)((warpRow + mi * 16 + arow) * LDA + k0 + acol) * 2;
                ldsm4(aH[mi], aBH + off);
                ldsm4(aL[mi], aBL + off);
            }
            uint32_t bH[8][2], bL[8][2];
#pragma unroll
            for (int nq = 0; nq < 4; nq++) {
                uint32_t off = (uint32_t)((k0 + arow) * LDB + warpCol + nq * 16 + acol) * 2;
                uint32_t r[4];
                ldsm4t(r, bBH + off);
                bH[nq * 2][0] = r[0]; bH[nq * 2][1] = r[1];
                bH[nq * 2 + 1][0] = r[2]; bH[nq * 2 + 1][1] = r[3];
                ldsm4t(r, bBL + off);
                bL[nq * 2][0] = r[0]; bL[nq * 2][1] = r[1];
                bL[nq * 2 + 1][0] = r[2]; bL[nq * 2 + 1][1] = r[3];
            }
#pragma unroll
            for (int mi = 0; mi < 2; mi++)
#pragma unroll
                for (int ni = 0; ni < 8; ni++) {
                    mma_bf16(acc[mi][ni], aH[mi], bH[ni]);
                    mma_bf16(acc[mi][ni], aH[mi], bL[ni]);
                    mma_bf16(acc[mi][ni], aL[mi], bH[ni]);
                }
        }
        __syncthreads();
    }
    // --- epilogue: write K-split partials ---
    int g = lane >> 2, tg = lane & 3;
    float* dp = d_part + (size_t)ks * (B_ * U_);
#pragma unroll
    for (int mi = 0; mi < 2; mi++)
#pragma unroll
        for (int ni = 0; ni < 8; ni++) {
            int row = rowBase + warpRow + mi * 16 + g;
            int col = colBase + warpCol + ni * 8 + tg * 2;
            *(float2*)&dp[(size_t)row * 512 + col] = make_float2(acc[mi][ni][0], acc[mi][ni][1]);
            *(float2*)&dp[(size_t)(row + 8) * 512 + col] = make_float2(acc[mi][ni][2], acc[mi][ni][3]);
        }
}

// ---------- K2b: deterministic K-split reduce ----------
__global__ __launch_bounds__(256) void k_red() {
    int idx = blockIdx.x * 256 + threadIdx.x;
    float s = 0.f;
#pragma unroll
    for (int ks = 0; ks < 4; ks++) s += d_part[(size_t)ks * (B_ * U_) + idx];
    d_h1[idx] = s;
}

// ---------- K3: head ----------
__global__ __launch_bounds__(128) void k_head(const float* __restrict__ g2g,
                                              const float* __restrict__ g2b,
                                              const float* __restrict__ k2base,
                                              const float* __restrict__ k2spl,
                                              const float* __restrict__ gw, const float* __restrict__ gb,
                                              const float* __restrict__ sw, const float* __restrict__ sb,
                                              const float* __restrict__ lg, const float* __restrict__ lb) {
    __shared__ float sh[128];
    int b = blockIdx.x, t = threadIdx.x;
    float v[4], S = 0.f, Q = 0.f;
#pragma unroll
    for (int m = 0; m < 4; m++) {
        v[m] = d_h1[b * 512 + t + 128 * m];
        S += v[m]; Q += v[m] * v[m];
    }
    S = red128(S, sh); Q = red128(Q, sh);
    float mean = S / 512.f;
    float rstd = rsqrtf(Q / 512.f - mean * mean + 1e-3f);
    float a0 = 0.f, a1 = 0.f, a2 = 0.f;
#pragma unroll
    for (int m = 0; m < 4; m++) {
        int i = t + 128 * m;
        float xn = (v[m] - mean) * rstd * g2g[i] + g2b[i];
        float e[9];
        kan_expand(xn, e);
        a0 += e[0] * k2base[i * 3 + 0];
        a1 += e[0] * k2base[i * 3 + 1];
        a2 += e[0] * k2base[i * 3 + 2];
#pragma unroll
        for (int j = 0; j < 8; j++) {
            const float* sp = k2spl + (size_t)(i * 8 + j) * 3;
            a0 += e[1 + j] * sp[0];
            a1 += e[1 + j] * sp[1];
            a2 += e[1 + j] * sp[2];
        }
    }
    a0 = red128(a0, sh); a1 = red128(a1, sh); a2 = red128(a2, sh);
    if (t == 0) {
        float h2[3] = {a0, a1, a2};
        float y[3];
#pragma unroll
        for (int o = 0; o < 3; o++) {
            float g1 = gb[o], s1 = sb[o];
#pragma unroll
            for (int p = 0; p < 3; p++) { g1 += h2[p] * gw[p * 3 + o]; s1 += h2[p] * sw[p * 3 + o]; }
            y[o] = d_skip[b * 3 + o] + g1 * sigm(s1);
        }
        float m = (y[0] + y[1] + y[2]) * (1.f / 3.f);
        float var = ((y[0] - m) * (y[0] - m) + (y[1] - m) * (y[1] - m) + (y[2] - m) * (y[2] - m)) * (1.f / 3.f);
        float rs = rsqrtf(var + 1e-3f);
        float yn[3], mx = -1e30f;
#pragma unroll
        for (int o = 0; o < 3; o++) { yn[o] = (y[o] - m) * rs * lg[o] + lb[o]; mx = fmaxf(mx, yn[o]); }
        float e0 = __expf(yn[0] - mx), e1 = __expf(yn[1] - mx), e2 = __expf(yn[2] - mx);
        float inv = 1.f / (e0 + e1 + e2);
        d_sigw[b * 3 + 0] = e0 * inv;
        d_sigw[b * 3 + 1] = e1 * inv;
        d_sigw[b * 3 + 2] = e2 * inv;
    }
}

// ---------- K4: LSTM gates ----------
__global__ __launch_bounds__(256) void k_z(const float* __restrict__ x, const float* __restrict__ h0,
                                           const float* __restrict__ W1, const float* __restrict__ W2,
                                           const float* __restrict__ bias) {
    __shared__ float As[16 * 64], Bs[16 * 64];
    int tid = threadIdx.x;
    int rowBase = blockIdx.y * 64, colBase = blockIdx.x * 64;
    int r0 = (tid >> 4) * 4, c0 = (tid & 15) * 4;
    float acc[4][4] = {};
    for (int kt = 0; kt < 640; kt += 16) {
        for (int idx = tid; idx < 1024; idx += 256) {
            int kk = idx & 15, m = idx >> 4, kg = kt + kk, b = rowBase + m;
            As[kk * 64 + m] = (kg < 128) ? x[b * 128 + kg] : h0[b * 512 + kg - 128];
            int cc = idx & 63, k2 = idx >> 6, kg2 = kt + k2, c = colBase + cc;
            Bs[k2 * 64 + cc] = (kg2 < 128) ? W1[kg2 * 1536 + c] : W2[(size_t)(kg2 - 128) * 1536 + c];
        }
        __syncthreads();
#pragma unroll
        for (int k = 0; k < 16; k++) {
            float4 a = *(const float4*)&As[k * 64 + r0];
            float4 bb = *(const float4*)&Bs[k * 64 + c0];
            float av[4] = {a.x, a.y, a.z, a.w}, bv[4] = {bb.x, bb.y, bb.z, bb.w};
#pragma unroll
            for (int i = 0; i < 4; i++)
#pragma unroll
                for (int j = 0; j < 4; j++) acc[i][j] += av[i] * bv[j];
        }
        __syncthreads();
    }
#pragma unroll
    for (int i = 0; i < 4; i++)
#pragma unroll
        for (int j = 0; j < 4; j++) {
            int b = rowBase + r0 + i, c = colBase + c0 + j;
            d_z[b * 1536 + c] = sigm(acc[i][j] + bias[c]);
        }
}

// ---------- K5: agg_in ----------
__global__ __launch_bounds__(256) void k_aggin(const float* __restrict__ x, const float* __restrict__ ss,
                                               const float* __restrict__ rki, const float* __restrict__ rks) {
    __shared__ float As[16 * 64], Bs[16 * 64];
    int tid = threadIdx.x, n = blockIdx.z;
    int rowBase = blockIdx.y * 64, colBase = blockIdx.x * 64;
    int r0 = (tid >> 4) * 4, c0 = (tid & 15) * 4;
    float acc[4][4] = {};
    for (int kt = 0; kt < 256; kt += 16) {
        for (int idx = tid; idx < 1024; idx += 256) {
            int kk = idx & 15, m = idx >> 4, kg = kt + kk, b = rowBase + m;
            As[kk * 64 + m] = (kg < 128) ? x[b * 128 + kg] : ss[n * 131072 + b * 128 + kg - 128];
            int cc = idx & 63, k2 = idx >> 6, kg2 = kt + k2, c = colBase + cc;
            Bs[k2 * 64 + cc] = (kg2 < 128) ? rki[n * 16384 + kg2 * 128 + c]
                                           : rks[n * 16384 + (kg2 - 128) * 128 + c];
        }
        __syncthreads();
#pragma unroll
        for (int k = 0; k < 16; k++) {
            float4 a = *(const float4*)&As[k * 64 + r0];
            float4 bb = *(const float4*)&Bs[k * 64 + c0];
            float av[4] = {a.x, a.y, a.z, a.w}, bv[4] = {bb.x, bb.y, bb.z, bb.w};
#pragma unroll
            for (int i = 0; i < 4; i++)
#pragma unroll
                for (int j = 0; j < 4; j++) acc[i][j] += av[i] * bv[j];
        }
        __syncthreads();
    }
#pragma unroll
    for (int i = 0; i < 4; i++)
#pragma unroll
        for (int j = 0; j < 4; j++)
            d_aggin[n * 131072 + (rowBase + r0 + i) * 128 + colBase + c0 + j] = acc[i][j];
}

// ---------- K6: sub LN + expansion ----------
__global__ __launch_bounds__(128) void k_subexpand(const float* __restrict__ lg,
                                                   const float* __restrict__ lb) {
    __shared__ float sh[128];
    int bx = blockIdx.x, t = threadIdx.x;
    int n = bx >> 10;
    float v = d_aggin[bx * 128 + t];
    float S = red128(v, sh), Q = red128(v * v, sh);
    float mean = S * (1.f / 128.f);
    float rstd = rsqrtf(Q * (1.f / 128.f) - mean * mean + 1e-3f);
    float xn = (v - mean) * rstd * lg[n * 128 + t] + lb[n * 128 + t];
    float e[9];
    kan_expand(xn, e);
    size_t base = (size_t)bx * 1152 + t * 9;
#pragma unroll
    for (int j = 0; j < 9; j++) d_subE[base + j] = e[j];
}

// ---------- K7: pack sub weights ----------
__global__ void k_packW(const float* __restrict__ bw, const float* __restrict__ sw) {
    int idx = blockIdx.x * 256 + threadIdx.x;
    if (idx >= 3 * 1152 * 128) return;
    int n = idx / 147456, rem = idx - n * 147456;
    int k = rem >> 7, o = rem & 127;
    int f = k / 9, j = k - f * 9;
    d_subW[idx] = (j == 0) ? bw[n * 16384 + f * 128 + o]
                           : sw[n * 131072 + (f * 8 + j - 1) * 128 + o];
}

// ---------- K8: sub GEMM + epilogue ----------
__global__ __launch_bounds__(256) void k_subgemm(const float* __restrict__ ss,
                                                 const float* __restrict__ subk,
                                                 float* __restrict__ out_ss) {
    __shared__ float As[16 * 64], Bs[16 * 64];
    int tid = threadIdx.x, n = blockIdx.z;
    int rowBase = blockIdx.y * 64, colBase = blockIdx.x * 64;
    int r0 = (tid >> 4) * 4, c0 = (tid & 15) * 4;
    float acc[4][4] = {};
    for (int kt = 0; kt < 1152; kt += 16) {
        for (int idx = tid; idx < 1024; idx += 256) {
            int kk = idx & 15, m = idx >> 4, b = rowBase + m;
            As[kk * 64 + m] = d_subE[((size_t)(n * 1024 + b)) * 1152 + kt + kk];
            int cc = idx & 63, k2 = idx >> 6, c = colBase + cc;
            Bs[k2 * 64 + cc] = d_subW[n * 147456 + (kt + k2) * 128 + c];
        }
        __syncthreads();
#pragma unroll
        for (int k = 0; k < 16; k++) {
            float4 a = *(const float4*)&As[k * 64 + r0];
            float4 bb = *(const float4*)&Bs[k * 64 + c0];
            float av[4] = {a.x, a.y, a.z, a.w}, bv[4] = {bb.x, bb.y, bb.z, bb.w};
#pragma unroll
            for (int i = 0; i < 4; i++)
#pragma unroll
                for (int j = 0; j < 4; j++) acc[i][j] += av[i] * bv[j];
        }
        __syncthreads();
    }
#pragma unroll
    for (int i = 0; i < 4; i++)
#pragma unroll
        for (int j = 0; j < 4; j++) {
            int b = rowBase + r0 + i, o = colBase + c0 + j;
            float v = acc[i][j] * d_sigw[b * 3 + n];
            d_agg[b * 384 + n * 128 + o] = v;
            out_ss[n * 131072 + b * 128 + o] =
                subk[n * 256 + o] * v + ss[n * 131072 + b * 128 + o] * subk[n * 256 + 128 + o];
        }
}

// ---------- K9: x_o GEMM + final c, h ----------
__global__ __launch_bounds__(256) void k_final(const float* __restrict__ aw, const float* __restrict__ ab,
                                               const float* __restrict__ c0p, float* __restrict__ out) {
    __shared__ float As[16 * 64], Bs[16 * 64];
    int tid = threadIdx.x;
    int rowBase = blockIdx.y * 64, colBase = blockIdx.x * 64;
    int r0 = (tid >> 4) * 4, cc0 = (tid & 15) * 4;
    float acc[4][4] = {};
    for (int kt = 0; kt < 384; kt += 16) {
        for (int idx = tid; idx < 1024; idx += 256) {
            int kk = idx & 15, m = idx >> 4;
            As[kk * 64 + m] = d_agg[(rowBase + m) * 384 + kt + kk];
            int cc = idx & 63, k2 = idx >> 6;
            Bs[k2 * 64 + cc] = aw[(kt + k2) * 512 + colBase + cc];
        }
        __syncthreads();
#pragma unroll
        for (int k = 0; k < 16; k++) {
            float4 a = *(const float4*)&As[k * 64 + r0];
            float4 bb = *(const float4*)&Bs[k * 64 + cc0];
            float av[4] = {a.x, a.y, a.z, a.w}, bv[4] = {bb.x, bb.y, bb.z, bb.w};
#pragma unroll
            for (int i = 0; i < 4; i++)
#pragma unroll
                for (int j = 0; j < 4; j++) acc[i][j] += av[i] * bv[j];
        }
        __syncthreads();
    }
#pragma unroll
    for (int i = 0; i < 4; i++)
#pragma unroll
        for (int j = 0; j < 4; j++) {
            int b = rowBase + r0 + i, c = colBase + cc0 + j;
            float xo = sigm(acc[i][j] + ab[c]);
            float zi = d_z[b * 1536 + c];
            float zf = d_z[b * 1536 + 512 + c];
            float zc = d_z[b * 1536 + 1024 + c];
            float cv = zf * c0p[b * 512 + c] + zi * zc;
            out[b * 512 + c] = xo * tanhf(cv);
            out[B_ * U_ + b * 512 + c] = cv;
        }
}

// ---------- launch ----------
extern "C" void kernel_launch(void* const* d_in, const int* in_sizes, int n_in,
                              void* d_out, int out_size) {
    const float* inputs   = (const float*)d_in[0];
    const float* h0       = (const float*)d_in[1];
    const float* c0       = (const float*)d_in[2];
    const float* sub_st   = (const float*)d_in[3];
    const float* kern     = (const float*)d_in[4];
    const float* rkern    = (const float*)d_in[5];
    const float* bias     = (const float*)d_in[6];
    const float* sub_k    = (const float*)d_in[7];
    const float* sub_rki  = (const float*)d_in[8];
    const float* sub_rks  = (const float*)d_in[9];
    const float* agg_w    = (const float*)d_in[10];
    const float* agg_b    = (const float*)d_in[11];
    const float* sub_lng  = (const float*)d_in[12];
    const float* sub_lnb  = (const float*)d_in[13];
    const float* sub_bw   = (const float*)d_in[14];
    const float* sub_sw   = (const float*)d_in[15];
    const float* g_skw    = (const float*)d_in[16];
    const float* g_skb    = (const float*)d_in[17];
    const float* k1_lng   = (const float*)d_in[18];
    const float* k1_lnb   = (const float*)d_in[19];
    const float* k1_base  = (const float*)d_in[20];
    const float* k1_spl   = (const float*)d_in[21];
    const float* k2_lng   = (const float*)d_in[22];
    const float* k2_lnb   = (const float*)d_in[23];
    const float* k2_base  = (const float*)d_in[24];
    const float* k2_spl   = (const float*)d_in[25];
    const float* gw       = (const float*)d_in[26];
    const float* gb       = (const float*)d_in[27];
    const float* sw       = (const float*)d_in[28];
    const float* sb       = (const float*)d_in[29];
    const float* lg       = (const float*)d_in[30];
    const float* lb       = (const float*)d_in[31];
    float* out = (float*)d_out;

    static bool attr_set = false;
    if (!attr_set) {
        cudaFuncSetAttribute(k_mma, cudaFuncAttributeMaxDynamicSharedMemorySize, SM_MMA);
        attr_set = true;
    }

    k_stats<<<B_, 128>>>(inputs, g_skw, g_skb);
    k_mma<<<dim3(4, 8, 4), 256, SM_MMA>>>(inputs, k1_lng, k1_lnb, k1_base, k1_spl);
    k_red<<<2048, 256>>>();
    k_head<<<B_, 128>>>(k2_lng, k2_lnb, k2_base, k2_spl, gw, gb, sw, sb, lg, lb);
    k_z<<<dim3(24, 16), 256>>>(inputs, h0, kern, rkern, bias);
    k_aggin<<<dim3(2, 16, 3), 256>>>(inputs, sub_st, sub_rki, sub_rks);
    k_subexpand<<<3 * B_, 128>>>(sub_lng, sub_lnb);
    k_packW<<<(3 * 1152 * 128 + 255) / 256, 256>>>(sub_bw, sub_sw);
    k_subgemm<<<dim3(2, 16, 3), 256>>>(sub_st, sub_k, out + 2 * B_ * U_);
    k_final<<<dim3(8, 16), 256>>>(agg_w, agg_b, c0, out);
}

// round 8
// speedup vs baseline: 2.8584x; 1.3176x over previous
#include <cuda_runtime.h>
#include <cuda_bf16.h>
#include <stdint.h>

#define DEV __device__ __forceinline__
typedef unsigned long long ull;

#define B_ 1024
#define U_ 512
#define SIGD 16512

// ---------- scratch ----------
__device__ float d_mu[B_];
__device__ float d_rstd[B_];
__device__ float d_skip[B_ * 3];
__device__ float d_sigw[B_ * 3];
__device__ __align__(16) float d_z[B_ * 1536];
__device__ __align__(16) float d_h1[B_ * U_];
__device__ __align__(16) float d_aggin[3 * B_ * 128];
__device__ __align__(16) float d_subE[3 * B_ * 1152];
__device__ __align__(16) float d_subW[3 * 1152 * 128];
__device__ __align__(16) float d_agg[B_ * 384];
__device__ __align__(16) float d_part[4 * B_ * U_];

// ---------- helpers ----------
DEV float sigm(float x) { return 1.f / (1.f + __expf(-x)); }
DEV uint32_t f2tf(float f) {
    uint32_t r;
    asm("cvt.rna.tf32.f32 %0,%1;" : "=r"(r) : "f"(f));
    return r;
}
DEV void mma_tf32(float acc[4], const uint32_t a[4], const uint32_t b[2]) {
    asm volatile(
        "mma.sync.aligned.m16n8k8.row.col.f32.tf32.tf32.f32 "
        "{%0,%1,%2,%3},{%4,%5,%6,%7},{%8,%9},{%0,%1,%2,%3};"
        : "+f"(acc[0]), "+f"(acc[1]), "+f"(acc[2]), "+f"(acc[3])
        : "r"(a[0]), "r"(a[1]), "r"(a[2]), "r"(a[3]), "r"(b[0]), "r"(b[1]));
}

DEV void kan_expand(float xn, float e[9]) {
    e[0] = xn * sigm(xn);
#pragma unroll
    for (int j = 1; j < 9; j++) e[j] = 0.f;
    float tp = (xn + 2.2f) * 2.5f;
    float tf = floorf(tp);
    if (tf >= 0.f && tf <= 10.f) {
        int t = (int)tf;
        float u = tp - tf, u2 = u * u, u3 = u2 * u, omu = 1.f - u;
        float v0 = omu * omu * omu * (1.f / 6.f);
        float v1 = (3.f * u3 - 6.f * u2 + 4.f) * (1.f / 6.f);
        float v2 = (-3.f * u3 + 3.f * u2 + 3.f * u + 1.f) * (1.f / 6.f);
        float v3 = u3 * (1.f / 6.f);
        if (t >= 3)           e[t - 2] = v0;
        if (t >= 2 && t <= 9) e[t - 1] = v1;
        if (t >= 1 && t <= 8) e[t]     = v2;
        if (t <= 7)           e[t + 1] = v3;
    }
}

DEV float red128(float v, float* sh) {
    int t = threadIdx.x;
    sh[t] = v; __syncthreads();
#pragma unroll
    for (int s = 64; s > 0; s >>= 1) { if (t < s) sh[t] += sh[t + s]; __syncthreads(); }
    float r = sh[0]; __syncthreads();
    return r;
}

// ---------- K1: sig LN stats (closed form) + skip ----------
__global__ __launch_bounds__(128) void k_stats(const float* __restrict__ x,
                                               const float* __restrict__ skw,
                                               const float* __restrict__ skb) {
    __shared__ float xs[128], sh[128];
    int b = blockIdx.x, t = threadIdx.x;
    float xv = x[b * 128 + t];
    xs[t] = xv; __syncthreads();
    float S = red128(xv, sh);
    float Q = red128(xv * xv, sh);
    if (t == 0) {
        float mean = (S + 0.5f * S * S) / (float)SIGD;
        float m2 = (Q + 0.25f * Q * Q) / (float)SIGD;
        d_mu[b] = mean;
        d_rstd[b] = rsqrtf(m2 - mean * mean + 1e-3f);
    }
    float a0 = 0.f, a1 = 0.f, a2 = 0.f;
    for (int i = t; i < SIGD; i += 128) {
        float sv = (i < 128) ? xs[i] : 0.5f * xs[(i - 128) >> 7] * xs[(i - 128) & 127];
        a0 += sv * skw[i * 3 + 0];
        a1 += sv * skw[i * 3 + 1];
        a2 += sv * skw[i * 3 + 2];
    }
    a0 = red128(a0, sh); a1 = red128(a1, sh); a2 = red128(a2, sh);
    if (t == 0) {
        d_skip[b * 3 + 0] = a0 + skb[0];
        d_skip[b * 3 + 1] = a1 + skb[1];
        d_skip[b * 3 + 2] = a2 + skb[2];
    }
}

// ---------- K2: big KAN GEMM via mma.sync tf32 (single product) ----------
// grid (ks=4, mg=8, ng=4) = 128 CTAs. Tile 128 rows x 128 cols.
// Chunks of 16 features = 144 k-units = 18 mma k-steps (k=8).
#define LDA4 148
#define LDB4 136
#define SM_MMA (128 * LDA4 * 4 + 144 * LDB4 * 4)   // 154112
__global__ __launch_bounds__(256, 1) void k_mma(const float* __restrict__ x,
                                                const float* __restrict__ lng,
                                                const float* __restrict__ lnb,
                                                const float* __restrict__ wb,
                                                const float* __restrict__ ws) {
    extern __shared__ uint32_t sm4[];
    uint32_t* As4 = sm4;                 // [row][k] tf32, pad 148
    uint32_t* Bs4 = sm4 + 128 * LDA4;    // [k][n]  tf32, pad 136

    int tid = threadIdx.x, lane = tid & 31, wid = tid >> 5;
    int ks = blockIdx.x, mg = blockIdx.y, ng = blockIdx.z;
    int rowBase = mg * 128, colBase = ng * 128;
    int warpRow = (wid & 3) * 32, warpCol = (wid >> 2) * 64;
    int g = lane >> 2, tg = lane & 3;
    int rsel = tid >> 5, n4 = (tid & 31) * 4;

    float acc[2][8][4];
#pragma unroll
    for (int mi = 0; mi < 2; mi++)
#pragma unroll
        for (int ni = 0; ni < 8; ni++)
#pragma unroll
            for (int q = 0; q < 4; q++) acc[mi][ni][q] = 0.f;

    for (int ch = 0; ch < 258; ch++) {
        int f0 = ks * 4128 + ch * 16;
        // --- A: expand 16 feats x 128 rows into tf32 smem ---
#pragma unroll
        for (int p = 0; p < 8; p++) {
            int task = tid + p * 256;
            int fl = task & 15, row = task >> 4;
            int fg = f0 + fl;
            const float* xr = x + (size_t)(rowBase + row) * 128;
            float val;
            if (fg < 128) val = __ldg(xr + fg);
            else {
                int q = fg - 128;
                val = 0.5f * __ldg(xr + (q >> 7)) * __ldg(xr + (q & 127));
            }
            float xn = (val - d_mu[rowBase + row]) * d_rstd[rowBase + row]
                     * __ldg(lng + fg) + __ldg(lnb + fg);
            float e[9];
            kan_expand(xn, e);
            int off = row * LDA4 + fl * 9;
#pragma unroll
            for (int j = 0; j < 9; j++) As4[off + j] = f2tf(e[j]);
        }
        // --- B: load 144 x 128 fp32, cvt tf32, store [k][n] ---
#pragma unroll
        for (int i = 0; i < 18; i++) {
            int kl = i * 8 + rsel;
            int kg = f0 * 9 + kl;
            int f = kg / 9, jj = kg - f * 9;
            const float* p = (jj == 0) ? wb + (size_t)f * 512
                                       : ws + ((size_t)f * 8 + (jj - 1)) * 512;
            float4 v = *(const float4*)(p + colBase + n4);
            uint4 w;
            w.x = f2tf(v.x); w.y = f2tf(v.y); w.z = f2tf(v.z); w.w = f2tf(v.w);
            *(uint4*)&Bs4[kl * LDB4 + n4] = w;
        }
        __syncthreads();
        // --- MMA: 18 k-steps of 8 ---
#pragma unroll 1
        for (int ks2 = 0; ks2 < 18; ks2++) {
            int k0 = ks2 * 8;
            uint32_t aF[2][4];
#pragma unroll
            for (int mi = 0; mi < 2; mi++) {
                int r = warpRow + mi * 16;
                aF[mi][0] = As4[(r + g) * LDA4 + k0 + tg];
                aF[mi][1] = As4[(r + 8 + g) * LDA4 + k0 + tg];
                aF[mi][2] = As4[(r + g) * LDA4 + k0 + tg + 4];
                aF[mi][3] = As4[(r + 8 + g) * LDA4 + k0 + tg + 4];
            }
            uint32_t bF[8][2];
#pragma unroll
            for (int ni = 0; ni < 8; ni++) {
                int c = warpCol + ni * 8 + g;
                bF[ni][0] = Bs4[(k0 + tg) * LDB4 + c];
                bF[ni][1] = Bs4[(k0 + tg + 4) * LDB4 + c];
            }
#pragma unroll
            for (int mi = 0; mi < 2; mi++)
#pragma unroll
                for (int ni = 0; ni < 8; ni++)
                    mma_tf32(acc[mi][ni], aF[mi], bF[ni]);
        }
        __syncthreads();
    }
    // --- epilogue: write K-split partials ---
    float* dp = d_part + (size_t)ks * (B_ * U_);
#pragma unroll
    for (int mi = 0; mi < 2; mi++)
#pragma unroll
        for (int ni = 0; ni < 8; ni++) {
            int row = rowBase + warpRow + mi * 16 + g;
            int col = colBase + warpCol + ni * 8 + tg * 2;
            *(float2*)&dp[(size_t)row * 512 + col] = make_float2(acc[mi][ni][0], acc[mi][ni][1]);
            *(float2*)&dp[(size_t)(row + 8) * 512 + col] = make_float2(acc[mi][ni][2], acc[mi][ni][3]);
        }
}

// ---------- K2b: deterministic K-split reduce ----------
__global__ __launch_bounds__(256) void k_red() {
    int idx = blockIdx.x * 256 + threadIdx.x;
    float s = 0.f;
#pragma unroll
    for (int ks = 0; ks < 4; ks++) s += d_part[(size_t)ks * (B_ * U_) + idx];
    d_h1[idx] = s;
}

// ---------- K3: head ----------
__global__ __launch_bounds__(128) void k_head(const float* __restrict__ g2g,
                                              const float* __restrict__ g2b,
                                              const float* __restrict__ k2base,
                                              const float* __restrict__ k2spl,
                                              const float* __restrict__ gw, const float* __restrict__ gb,
                                              const float* __restrict__ sw, const float* __restrict__ sb,
                                              const float* __restrict__ lg, const float* __restrict__ lb) {
    __shared__ float sh[128];
    int b = blockIdx.x, t = threadIdx.x;
    float v[4], S = 0.f, Q = 0.f;
#pragma unroll
    for (int m = 0; m < 4; m++) {
        v[m] = d_h1[b * 512 + t + 128 * m];
        S += v[m]; Q += v[m] * v[m];
    }
    S = red128(S, sh); Q = red128(Q, sh);
    float mean = S / 512.f;
    float rstd = rsqrtf(Q / 512.f - mean * mean + 1e-3f);
    float a0 = 0.f, a1 = 0.f, a2 = 0.f;
#pragma unroll
    for (int m = 0; m < 4; m++) {
        int i = t + 128 * m;
        float xn = (v[m] - mean) * rstd * g2g[i] + g2b[i];
        float e[9];
        kan_expand(xn, e);
        a0 += e[0] * k2base[i * 3 + 0];
        a1 += e[0] * k2base[i * 3 + 1];
        a2 += e[0] * k2base[i * 3 + 2];
#pragma unroll
        for (int j = 0; j < 8; j++) {
            const float* sp = k2spl + (size_t)(i * 8 + j) * 3;
            a0 += e[1 + j] * sp[0];
            a1 += e[1 + j] * sp[1];
            a2 += e[1 + j] * sp[2];
        }
    }
    a0 = red128(a0, sh); a1 = red128(a1, sh); a2 = red128(a2, sh);
    if (t == 0) {
        float h2[3] = {a0, a1, a2};
        float y[3];
#pragma unroll
        for (int o = 0; o < 3; o++) {
            float g1 = gb[o], s1 = sb[o];
#pragma unroll
            for (int p = 0; p < 3; p++) { g1 += h2[p] * gw[p * 3 + o]; s1 += h2[p] * sw[p * 3 + o]; }
            y[o] = d_skip[b * 3 + o] + g1 * sigm(s1);
        }
        float m = (y[0] + y[1] + y[2]) * (1.f / 3.f);
        float var = ((y[0] - m) * (y[0] - m) + (y[1] - m) * (y[1] - m) + (y[2] - m) * (y[2] - m)) * (1.f / 3.f);
        float rs = rsqrtf(var + 1e-3f);
        float yn[3], mx = -1e30f;
#pragma unroll
        for (int o = 0; o < 3; o++) { yn[o] = (y[o] - m) * rs * lg[o] + lb[o]; mx = fmaxf(mx, yn[o]); }
        float e0 = __expf(yn[0] - mx), e1 = __expf(yn[1] - mx), e2 = __expf(yn[2] - mx);
        float inv = 1.f / (e0 + e1 + e2);
        d_sigw[b * 3 + 0] = e0 * inv;
        d_sigw[b * 3 + 1] = e1 * inv;
        d_sigw[b * 3 + 2] = e2 * inv;
    }
}

// ---------- K4: LSTM gates ----------
__global__ __launch_bounds__(256) void k_z(const float* __restrict__ x, const float* __restrict__ h0,
                                           const float* __restrict__ W1, const float* __restrict__ W2,
                                           const float* __restrict__ bias) {
    __shared__ float As[16 * 64], Bs[16 * 64];
    int tid = threadIdx.x;
    int rowBase = blockIdx.y * 64, colBase = blockIdx.x * 64;
    int r0 = (tid >> 4) * 4, c0 = (tid & 15) * 4;
    float acc[4][4] = {};
    for (int kt = 0; kt < 640; kt += 16) {
        for (int idx = tid; idx < 1024; idx += 256) {
            int kk = idx & 15, m = idx >> 4, kg = kt + kk, b = rowBase + m;
            As[kk * 64 + m] = (kg < 128) ? x[b * 128 + kg] : h0[b * 512 + kg - 128];
            int cc = idx & 63, k2 = idx >> 6, kg2 = kt + k2, c = colBase + cc;
            Bs[k2 * 64 + cc] = (kg2 < 128) ? W1[kg2 * 1536 + c] : W2[(size_t)(kg2 - 128) * 1536 + c];
        }
        __syncthreads();
#pragma unroll
        for (int k = 0; k < 16; k++) {
            float4 a = *(const float4*)&As[k * 64 + r0];
            float4 bb = *(const float4*)&Bs[k * 64 + c0];
            float av[4] = {a.x, a.y, a.z, a.w}, bv[4] = {bb.x, bb.y, bb.z, bb.w};
#pragma unroll
            for (int i = 0; i < 4; i++)
#pragma unroll
                for (int j = 0; j < 4; j++) acc[i][j] += av[i] * bv[j];
        }
        __syncthreads();
    }
#pragma unroll
    for (int i = 0; i < 4; i++)
#pragma unroll
        for (int j = 0; j < 4; j++) {
            int b = rowBase + r0 + i, c = colBase + c0 + j;
            d_z[b * 1536 + c] = sigm(acc[i][j] + bias[c]);
        }
}

// ---------- K5: agg_in ----------
__global__ __launch_bounds__(256) void k_aggin(const float* __restrict__ x, const float* __restrict__ ss,
                                               const float* __restrict__ rki, const float* __restrict__ rks) {
    __shared__ float As[16 * 64], Bs[16 * 64];
    int tid = threadIdx.x, n = blockIdx.z;
    int rowBase = blockIdx.y * 64, colBase = blockIdx.x * 64;
    int r0 = (tid >> 4) * 4, c0 = (tid & 15) * 4;
    float acc[4][4] = {};
    for (int kt = 0; kt < 256; kt += 16) {
        for (int idx = tid; idx < 1024; idx += 256) {
            int kk = idx & 15, m = idx >> 4, kg = kt + kk, b = rowBase + m;
            As[kk * 64 + m] = (kg < 128) ? x[b * 128 + kg] : ss[n * 131072 + b * 128 + kg - 128];
            int cc = idx & 63, k2 = idx >> 6, kg2 = kt + k2, c = colBase + cc;
            Bs[k2 * 64 + cc] = (kg2 < 128) ? rki[n * 16384 + kg2 * 128 + c]
                                           : rks[n * 16384 + (kg2 - 128) * 128 + c];
        }
        __syncthreads();
#pragma unroll
        for (int k = 0; k < 16; k++) {
            float4 a = *(const float4*)&As[k * 64 + r0];
            float4 bb = *(const float4*)&Bs[k * 64 + c0];
            float av[4] = {a.x, a.y, a.z, a.w}, bv[4] = {bb.x, bb.y, bb.z, bb.w};
#pragma unroll
            for (int i = 0; i < 4; i++)
#pragma unroll
                for (int j = 0; j < 4; j++) acc[i][j] += av[i] * bv[j];
        }
        __syncthreads();
    }
#pragma unroll
    for (int i = 0; i < 4; i++)
#pragma unroll
        for (int j = 0; j < 4; j++)
            d_aggin[n * 131072 + (rowBase + r0 + i) * 128 + colBase + c0 + j] = acc[i][j];
}

// ---------- K6: sub LN + expansion ----------
__global__ __launch_bounds__(128) void k_subexpand(const float* __restrict__ lg,
                                                   const float* __restrict__ lb) {
    __shared__ float sh[128];
    int bx = blockIdx.x, t = threadIdx.x;
    int n = bx >> 10;
    float v = d_aggin[bx * 128 + t];
    float S = red128(v, sh), Q = red128(v * v, sh);
    float mean = S * (1.f / 128.f);
    float rstd = rsqrtf(Q * (1.f / 128.f) - mean * mean + 1e-3f);
    float xn = (v - mean) * rstd * lg[n * 128 + t] + lb[n * 128 + t];
    float e[9];
    kan_expand(xn, e);
    size_t base = (size_t)bx * 1152 + t * 9;
#pragma unroll
    for (int j = 0; j < 9; j++) d_subE[base + j] = e[j];
}

// ---------- K7: pack sub weights ----------
__global__ void k_packW(const float* __restrict__ bw, const float* __restrict__ sw) {
    int idx = blockIdx.x * 256 + threadIdx.x;
    if (idx >= 3 * 1152 * 128) return;
    int n = idx / 147456, rem = idx - n * 147456;
    int k = rem >> 7, o = rem & 127;
    int f = k / 9, j = k - f * 9;
    d_subW[idx] = (j == 0) ? bw[n * 16384 + f * 128 + o]
                           : sw[n * 131072 + (f * 8 + j - 1) * 128 + o];
}

// ---------- K8: sub GEMM + epilogue ----------
__global__ __launch_bounds__(256) void k_subgemm(const float* __restrict__ ss,
                                                 const float* __restrict__ subk,
                                                 float* __restrict__ out_ss) {
    __shared__ float As[16 * 64], Bs[16 * 64];
    int tid = threadIdx.x, n = blockIdx.z;
    int rowBase = blockIdx.y * 64, colBase = blockIdx.x * 64;
    int r0 = (tid >> 4) * 4, c0 = (tid & 15) * 4;
    float acc[4][4] = {};
    for (int kt = 0; kt < 1152; kt += 16) {
        for (int idx = tid; idx < 1024; idx += 256) {
            int kk = idx & 15, m = idx >> 4, b = rowBase + m;
            As[kk * 64 + m] = d_subE[((size_t)(n * 1024 + b)) * 1152 + kt + kk];
            int cc = idx & 63, k2 = idx >> 6, c = colBase + cc;
            Bs[k2 * 64 + cc] = d_subW[n * 147456 + (kt + k2) * 128 + c];
        }
        __syncthreads();
#pragma unroll
        for (int k = 0; k < 16; k++) {
            float4 a = *(const float4*)&As[k * 64 + r0];
            float4 bb = *(const float4*)&Bs[k * 64 + c0];
            float av[4] = {a.x, a.y, a.z, a.w}, bv[4] = {bb.x, bb.y, bb.z, bb.w};
#pragma unroll
            for (int i = 0; i < 4; i++)
#pragma unroll
                for (int j = 0; j < 4; j++) acc[i][j] += av[i] * bv[j];
        }
        __syncthreads();
    }
#pragma unroll
    for (int i = 0; i < 4; i++)
#pragma unroll
        for (int j = 0; j < 4; j++) {
            int b = rowBase + r0 + i, o = colBase + c0 + j;
            float v = acc[i][j] * d_sigw[b * 3 + n];
            d_agg[b * 384 + n * 128 + o] = v;
            out_ss[n * 131072 + b * 128 + o] =
                subk[n * 256 + o] * v + ss[n * 131072 + b * 128 + o] * subk[n * 256 + 128 + o];
        }
}

// ---------- K9: x_o GEMM + final c, h ----------
__global__ __launch_bounds__(256) void k_final(const float* __restrict__ aw, const float* __restrict__ ab,
                                               const float* __restrict__ c0p, float* __restrict__ out) {
    __shared__ float As[16 * 64], Bs[16 * 64];
    int tid = threadIdx.x;
    int rowBase = blockIdx.y * 64, colBase = blockIdx.x * 64;
    int r0 = (tid >> 4) * 4, cc0 = (tid & 15) * 4;
    float acc[4][4] = {};
    for (int kt = 0; kt < 384; kt += 16) {
        for (int idx = tid; idx < 1024; idx += 256) {
            int kk = idx & 15, m = idx >> 4;
            As[kk * 64 + m] = d_agg[(rowBase + m) * 384 + kt + kk];
            int cc = idx & 63, k2 = idx >> 6;
            Bs[k2 * 64 + cc] = aw[(kt + k2) * 512 + colBase + cc];
        }
        __syncthreads();
#pragma unroll
        for (int k = 0; k < 16; k++) {
            float4 a = *(const float4*)&As[k * 64 + r0];
            float4 bb = *(const float4*)&Bs[k * 64 + cc0];
            float av[4] = {a.x, a.y, a.z, a.w}, bv[4] = {bb.x, bb.y, bb.z, bb.w};
#pragma unroll
            for (int i = 0; i < 4; i++)
#pragma unroll
                for (int j = 0; j < 4; j++) acc[i][j] += av[i] * bv[j];
        }
        __syncthreads();
    }
#pragma unroll
    for (int i = 0; i < 4; i++)
#pragma unroll
        for (int j = 0; j < 4; j++) {
            int b = rowBase + r0 + i, c = colBase + cc0 + j;
            float xo = sigm(acc[i][j] + ab[c]);
            float zi = d_z[b * 1536 + c];
            float zf = d_z[b * 1536 + 512 + c];
            float zc = d_z[b * 1536 + 1024 + c];
            float cv = zf * c0p[b * 512 + c] + zi * zc;
            out[b * 512 + c] = xo * tanhf(cv);
            out[B_ * U_ + b * 512 + c] = cv;
        }
}

// ---------- launch ----------
extern "C" void kernel_launch(void* const* d_in, const int* in_sizes, int n_in,
                              void* d_out, int out_size) {
    const float* inputs   = (const float*)d_in[0];
    const float* h0       = (const float*)d_in[1];
    const float* c0       = (const float*)d_in[2];
    const float* sub_st   = (const float*)d_in[3];
    const float* kern     = (const float*)d_in[4];
    const float* rkern    = (const float*)d_in[5];
    const float* bias     = (const float*)d_in[6];
    const float* sub_k    = (const float*)d_in[7];
    const float* sub_rki  = (const float*)d_in[8];
    const float* sub_rks  = (const float*)d_in[9];
    const float* agg_w    = (const float*)d_in[10];
    const float* agg_b    = (const float*)d_in[11];
    const float* sub_lng  = (const float*)d_in[12];
    const float* sub_lnb  = (const float*)d_in[13];
    const float* sub_bw   = (const float*)d_in[14];
    const float* sub_sw   = (const float*)d_in[15];
    const float* g_skw    = (const float*)d_in[16];
    const float* g_skb    = (const float*)d_in[17];
    const float* k1_lng   = (const float*)d_in[18];
    const float* k1_lnb   = (const float*)d_in[19];
    const float* k1_base  = (const float*)d_in[20];
    const float* k1_spl   = (const float*)d_in[21];
    const float* k2_lng   = (const float*)d_in[22];
    const float* k2_lnb   = (const float*)d_in[23];
    const float* k2_base  = (const float*)d_in[24];
    const float* k2_spl   = (const float*)d_in[25];
    const float* gw       = (const float*)d_in[26];
    const float* gb       = (const float*)d_in[27];
    const float* sw       = (const float*)d_in[28];
    const float* sb       = (const float*)d_in[29];
    const float* lg       = (const float*)d_in[30];
    const float* lb       = (const float*)d_in[31];
    float* out = (float*)d_out;

    static bool attr_set = false;
    if (!attr_set) {
        cudaFuncSetAttribute(k_mma, cudaFuncAttributeMaxDynamicSharedMemorySize, SM_MMA);
        attr_set = true;
    }

    k_stats<<<B_, 128>>>(inputs, g_skw, g_skb);
    k_mma<<<dim3(4, 8, 4), 256, SM_MMA>>>(inputs, k1_lng, k1_lnb, k1_base, k1_spl);
    k_red<<<2048, 256>>>();
    k_head<<<B_, 128>>>(k2_lng, k2_lnb, k2_base, k2_spl, gw, gb, sw, sb, lg, lb);
    k_z<<<dim3(24, 16), 256>>>(inputs, h0, kern, rkern, bias);
    k_aggin<<<dim3(2, 16, 3), 256>>>(inputs, sub_st, sub_rki, sub_rks);
    k_subexpand<<<3 * B_, 128>>>(sub_lng, sub_lnb);
    k_packW<<<(3 * 1152 * 128 + 255) / 256, 256>>>(sub_bw, sub_sw);
    k_subgemm<<<dim3(2, 16, 3), 256>>>(sub_st, sub_k, out + 2 * B_ * U_);
    k_final<<<dim3(8, 16), 256>>>(agg_w, agg_b, c0, out);
}

// round 9
// speedup vs baseline: 3.7399x; 1.3084x over previous
#include <cuda_runtime.h>
#include <cuda_bf16.h>
#include <stdint.h>

#define DEV __device__ __forceinline__
typedef unsigned long long ull;

#define B_ 1024
#define U_ 512
#define SIGD 16512

// ---------- scratch ----------
__device__ float d_mu[B_];
__device__ float d_rstd[B_];
__device__ float d_skip[B_ * 3];
__device__ float d_sigw[B_ * 3];
__device__ __align__(16) float d_z[B_ * 1536];
__device__ __align__(16) float d_h1[B_ * U_];
__device__ __align__(16) float d_aggin[3 * B_ * 128];
__device__ __align__(16) float d_subE[3 * B_ * 1152];
__device__ __align__(16) float d_subW[3 * 1152 * 128];
__device__ __align__(16) float d_agg[B_ * 384];
__device__ __align__(16) float d_part[8 * B_ * U_];

// ---------- helpers ----------
DEV float sigm(float x) { return 1.f / (1.f + __expf(-x)); }
DEV uint32_t f2tf(float f) {
    uint32_t r;
    asm("cvt.rna.tf32.f32 %0,%1;" : "=r"(r) : "f"(f));
    return r;
}
DEV void mma_tf32(float acc[4], const uint32_t a[4], const uint32_t b[2]) {
    asm volatile(
        "mma.sync.aligned.m16n8k8.row.col.f32.tf32.tf32.f32 "
        "{%0,%1,%2,%3},{%4,%5,%6,%7},{%8,%9},{%0,%1,%2,%3};"
        : "+f"(acc[0]), "+f"(acc[1]), "+f"(acc[2]), "+f"(acc[3])
        : "r"(a[0]), "r"(a[1]), "r"(a[2]), "r"(a[3]), "r"(b[0]), "r"(b[1]));
}

DEV void kan_expand(float xn, float e[9]) {
    e[0] = xn * sigm(xn);
#pragma unroll
    for (int j = 1; j < 9; j++) e[j] = 0.f;
    float tp = (xn + 2.2f) * 2.5f;
    float tf = floorf(tp);
    if (tf >= 0.f && tf <= 10.f) {
        int t = (int)tf;
        float u = tp - tf, u2 = u * u, u3 = u2 * u, omu = 1.f - u;
        float v0 = omu * omu * omu * (1.f / 6.f);
        float v1 = (3.f * u3 - 6.f * u2 + 4.f) * (1.f / 6.f);
        float v2 = (-3.f * u3 + 3.f * u2 + 3.f * u + 1.f) * (1.f / 6.f);
        float v3 = u3 * (1.f / 6.f);
        if (t >= 3)           e[t - 2] = v0;
        if (t >= 2 && t <= 9) e[t - 1] = v1;
        if (t >= 1 && t <= 8) e[t]     = v2;
        if (t <= 7)           e[t + 1] = v3;
    }
}

DEV float red128(float v, float* sh) {
    int t = threadIdx.x;
    sh[t] = v; __syncthreads();
#pragma unroll
    for (int s = 64; s > 0; s >>= 1) { if (t < s) sh[t] += sh[t + s]; __syncthreads(); }
    float r = sh[0]; __syncthreads();
    return r;
}

// ---------- K1: sig LN stats (closed form) + skip ----------
__global__ __launch_bounds__(128) void k_stats(const float* __restrict__ x,
                                               const float* __restrict__ skw,
                                               const float* __restrict__ skb) {
    __shared__ float xs[128], sh[128];
    int b = blockIdx.x, t = threadIdx.x;
    float xv = x[b * 128 + t];
    xs[t] = xv; __syncthreads();
    float S = red128(xv, sh);
    float Q = red128(xv * xv, sh);
    if (t == 0) {
        float mean = (S + 0.5f * S * S) / (float)SIGD;
        float m2 = (Q + 0.25f * Q * Q) / (float)SIGD;
        d_mu[b] = mean;
        d_rstd[b] = rsqrtf(m2 - mean * mean + 1e-3f);
    }
    float a0 = 0.f, a1 = 0.f, a2 = 0.f;
    for (int i = t; i < SIGD; i += 128) {
        float sv = (i < 128) ? xs[i] : 0.5f * xs[(i - 128) >> 7] * xs[(i - 128) & 127];
        a0 += sv * skw[i * 3 + 0];
        a1 += sv * skw[i * 3 + 1];
        a2 += sv * skw[i * 3 + 2];
    }
    a0 = red128(a0, sh); a1 = red128(a1, sh); a2 = red128(a2, sh);
    if (t == 0) {
        d_skip[b * 3 + 0] = a0 + skb[0];
        d_skip[b * 3 + 1] = a1 + skb[1];
        d_skip[b * 3 + 2] = a2 + skb[2];
    }
}

// ---------- K2: big KAN GEMM via mma.sync tf32, 2 CTAs/SM ----------
// grid (ks=8, mg=8, ng=4) = 256 CTAs, 2 per SM (78KB smem each).
// Chunk = 8 features = 72 k-units = 9 mma k-steps.
#define LDA4 76
#define LDB4 136
#define SM_MMA (128 * LDA4 * 4 + 72 * LDB4 * 4)   // 78080
__global__ __launch_bounds__(256, 2) void k_mma(const float* __restrict__ x,
                                                const float* __restrict__ lng,
                                                const float* __restrict__ lnb,
                                                const float* __restrict__ wb,
                                                const float* __restrict__ ws) {
    extern __shared__ uint32_t sm4[];
    uint32_t* As4 = sm4;                 // [row][k] tf32, pad 76
    uint32_t* Bs4 = sm4 + 128 * LDA4;    // [k][n]  tf32, pad 136

    int tid = threadIdx.x, lane = tid & 31, wid = tid >> 5;
    int ks = blockIdx.x, mg = blockIdx.y, ng = blockIdx.z;
    int rowBase = mg * 128, colBase = ng * 128;
    int warpRow = (wid & 3) * 32, warpCol = (wid >> 2) * 64;
    int g = lane >> 2, tg = lane & 3;
    int rsel = tid >> 5, n4 = (tid & 31) * 4;

    float acc[2][8][4];
#pragma unroll
    for (int mi = 0; mi < 2; mi++)
#pragma unroll
        for (int ni = 0; ni < 8; ni++)
#pragma unroll
            for (int q = 0; q < 4; q++) acc[mi][ni][q] = 0.f;

    for (int ch = 0; ch < 258; ch++) {
        int f0 = ks * 2064 + ch * 8;
        // --- A: expand 8 feats x 128 rows into tf32 smem ---
#pragma unroll
        for (int p = 0; p < 4; p++) {
            int task = tid + p * 256;
            int fl = task & 7, row = task >> 3;
            int fg = f0 + fl;
            const float* xr = x + (size_t)(rowBase + row) * 128;
            float val;
            if (fg < 128) val = __ldg(xr + fg);
            else {
                int q = fg - 128;
                val = 0.5f * __ldg(xr + (q >> 7)) * __ldg(xr + (q & 127));
            }
            float xn = (val - d_mu[rowBase + row]) * d_rstd[rowBase + row]
                     * __ldg(lng + fg) + __ldg(lnb + fg);
            float e[9];
            kan_expand(xn, e);
            int off = row * LDA4 + fl * 9;
#pragma unroll
            for (int j = 0; j < 9; j++) As4[off + j] = f2tf(e[j]);
        }
        // --- B: load 72 x 128 fp32, cvt tf32, store [k][n] ---
#pragma unroll
        for (int i = 0; i < 9; i++) {
            int kl = i * 8 + rsel;
            int kg = f0 * 9 + kl;
            int f = kg / 9, jj = kg - f * 9;
            const float* p = (jj == 0) ? wb + (size_t)f * 512
                                       : ws + ((size_t)f * 8 + (jj - 1)) * 512;
            float4 v = *(const float4*)(p + colBase + n4);
            uint4 w;
            w.x = f2tf(v.x); w.y = f2tf(v.y); w.z = f2tf(v.z); w.w = f2tf(v.w);
            *(uint4*)&Bs4[kl * LDB4 + n4] = w;
        }
        __syncthreads();
        // --- MMA: 9 k-steps of 8 ---
#pragma unroll 3
        for (int ks2 = 0; ks2 < 9; ks2++) {
            int k0 = ks2 * 8;
            uint32_t aF[2][4];
#pragma unroll
            for (int mi = 0; mi < 2; mi++) {
                int r = warpRow + mi * 16;
                aF[mi][0] = As4[(r + g) * LDA4 + k0 + tg];
                aF[mi][1] = As4[(r + 8 + g) * LDA4 + k0 + tg];
                aF[mi][2] = As4[(r + g) * LDA4 + k0 + tg + 4];
                aF[mi][3] = As4[(r + 8 + g) * LDA4 + k0 + tg + 4];
            }
            uint32_t bF[8][2];
#pragma unroll
            for (int ni = 0; ni < 8; ni++) {
                int c = warpCol + ni * 8 + g;
                bF[ni][0] = Bs4[(k0 + tg) * LDB4 + c];
                bF[ni][1] = Bs4[(k0 + tg + 4) * LDB4 + c];
            }
#pragma unroll
            for (int mi = 0; mi < 2; mi++)
#pragma unroll
                for (int ni = 0; ni < 8; ni++)
                    mma_tf32(acc[mi][ni], aF[mi], bF[ni]);
        }
        __syncthreads();
    }
    // --- epilogue: write K-split partials ---
    float* dp = d_part + (size_t)ks * (B_ * U_);
#pragma unroll
    for (int mi = 0; mi < 2; mi++)
#pragma unroll
        for (int ni = 0; ni < 8; ni++) {
            int row = rowBase + warpRow + mi * 16 + g;
            int col = colBase + warpCol + ni * 8 + tg * 2;
            *(float2*)&dp[(size_t)row * 512 + col] = make_float2(acc[mi][ni][0], acc[mi][ni][1]);
            *(float2*)&dp[(size_t)(row + 8) * 512 + col] = make_float2(acc[mi][ni][2], acc[mi][ni][3]);
        }
}

// ---------- K2b: deterministic K-split reduce ----------
__global__ __launch_bounds__(256) void k_red() {
    int idx = blockIdx.x * 256 + threadIdx.x;
    float s = 0.f;
#pragma unroll
    for (int ks = 0; ks < 8; ks++) s += d_part[(size_t)ks * (B_ * U_) + idx];
    d_h1[idx] = s;
}

// ---------- K3: head ----------
__global__ __launch_bounds__(128) void k_head(const float* __restrict__ g2g,
                                              const float* __restrict__ g2b,
                                              const float* __restrict__ k2base,
                                              const float* __restrict__ k2spl,
                                              const float* __restrict__ gw, const float* __restrict__ gb,
                                              const float* __restrict__ sw, const float* __restrict__ sb,
                                              const float* __restrict__ lg, const float* __restrict__ lb) {
    __shared__ float sh[128];
    int b = blockIdx.x, t = threadIdx.x;
    float v[4], S = 0.f, Q = 0.f;
#pragma unroll
    for (int m = 0; m < 4; m++) {
        v[m] = d_h1[b * 512 + t + 128 * m];
        S += v[m]; Q += v[m] * v[m];
    }
    S = red128(S, sh); Q = red128(Q, sh);
    float mean = S / 512.f;
    float rstd = rsqrtf(Q / 512.f - mean * mean + 1e-3f);
    float a0 = 0.f, a1 = 0.f, a2 = 0.f;
#pragma unroll
    for (int m = 0; m < 4; m++) {
        int i = t + 128 * m;
        float xn = (v[m] - mean) * rstd * g2g[i] + g2b[i];
        float e[9];
        kan_expand(xn, e);
        a0 += e[0] * k2base[i * 3 + 0];
        a1 += e[0] * k2base[i * 3 + 1];
        a2 += e[0] * k2base[i * 3 + 2];
#pragma unroll
        for (int j = 0; j < 8; j++) {
            const float* sp = k2spl + (size_t)(i * 8 + j) * 3;
            a0 += e[1 + j] * sp[0];
            a1 += e[1 + j] * sp[1];
            a2 += e[1 + j] * sp[2];
        }
    }
    a0 = red128(a0, sh); a1 = red128(a1, sh); a2 = red128(a2, sh);
    if (t == 0) {
        float h2[3] = {a0, a1, a2};
        float y[3];
#pragma unroll
        for (int o = 0; o < 3; o++) {
            float g1 = gb[o], s1 = sb[o];
#pragma unroll
            for (int p = 0; p < 3; p++) { g1 += h2[p] * gw[p * 3 + o]; s1 += h2[p] * sw[p * 3 + o]; }
            y[o] = d_skip[b * 3 + o] + g1 * sigm(s1);
        }
        float m = (y[0] + y[1] + y[2]) * (1.f / 3.f);
        float var = ((y[0] - m) * (y[0] - m) + (y[1] - m) * (y[1] - m) + (y[2] - m) * (y[2] - m)) * (1.f / 3.f);
        float rs = rsqrtf(var + 1e-3f);
        float yn[3], mx = -1e30f;
#pragma unroll
        for (int o = 0; o < 3; o++) { yn[o] = (y[o] - m) * rs * lg[o] + lb[o]; mx = fmaxf(mx, yn[o]); }
        float e0 = __expf(yn[0] - mx), e1 = __expf(yn[1] - mx), e2 = __expf(yn[2] - mx);
        float inv = 1.f / (e0 + e1 + e2);
        d_sigw[b * 3 + 0] = e0 * inv;
        d_sigw[b * 3 + 1] = e1 * inv;
        d_sigw[b * 3 + 2] = e2 * inv;
    }
}

// ---------- K4: LSTM gates ----------
__global__ __launch_bounds__(256) void k_z(const float* __restrict__ x, const float* __restrict__ h0,
                                           const float* __restrict__ W1, const float* __restrict__ W2,
                                           const float* __restrict__ bias) {
    __shared__ float As[16 * 64], Bs[16 * 64];
    int tid = threadIdx.x;
    int rowBase = blockIdx.y * 64, colBase = blockIdx.x * 64;
    int r0 = (tid >> 4) * 4, c0 = (tid & 15) * 4;
    float acc[4][4] = {};
    for (int kt = 0; kt < 640; kt += 16) {
        for (int idx = tid; idx < 1024; idx += 256) {
            int kk = idx & 15, m = idx >> 4, kg = kt + kk, b = rowBase + m;
            As[kk * 64 + m] = (kg < 128) ? x[b * 128 + kg] : h0[b * 512 + kg - 128];
            int cc = idx & 63, k2 = idx >> 6, kg2 = kt + k2, c = colBase + cc;
            Bs[k2 * 64 + cc] = (kg2 < 128) ? W1[kg2 * 1536 + c] : W2[(size_t)(kg2 - 128) * 1536 + c];
        }
        __syncthreads();
#pragma unroll
        for (int k = 0; k < 16; k++) {
            float4 a = *(const float4*)&As[k * 64 + r0];
            float4 bb = *(const float4*)&Bs[k * 64 + c0];
            float av[4] = {a.x, a.y, a.z, a.w}, bv[4] = {bb.x, bb.y, bb.z, bb.w};
#pragma unroll
            for (int i = 0; i < 4; i++)
#pragma unroll
                for (int j = 0; j < 4; j++) acc[i][j] += av[i] * bv[j];
        }
        __syncthreads();
    }
#pragma unroll
    for (int i = 0; i < 4; i++)
#pragma unroll
        for (int j = 0; j < 4; j++) {
            int b = rowBase + r0 + i, c = colBase + c0 + j;
            d_z[b * 1536 + c] = sigm(acc[i][j] + bias[c]);
        }
}

// ---------- K5: agg_in ----------
__global__ __launch_bounds__(256) void k_aggin(const float* __restrict__ x, const float* __restrict__ ss,
                                               const float* __restrict__ rki, const float* __restrict__ rks) {
    __shared__ float As[16 * 64], Bs[16 * 64];
    int tid = threadIdx.x, n = blockIdx.z;
    int rowBase = blockIdx.y * 64, colBase = blockIdx.x * 64;
    int r0 = (tid >> 4) * 4, c0 = (tid & 15) * 4;
    float acc[4][4] = {};
    for (int kt = 0; kt < 256; kt += 16) {
        for (int idx = tid; idx < 1024; idx += 256) {
            int kk = idx & 15, m = idx >> 4, kg = kt + kk, b = rowBase + m;
            As[kk * 64 + m] = (kg < 128) ? x[b * 128 + kg] : ss[n * 131072 + b * 128 + kg - 128];
            int cc = idx & 63, k2 = idx >> 6, kg2 = kt + k2, c = colBase + cc;
            Bs[k2 * 64 + cc] = (kg2 < 128) ? rki[n * 16384 + kg2 * 128 + c]
                                           : rks[n * 16384 + (kg2 - 128) * 128 + c];
        }
        __syncthreads();
#pragma unroll
        for (int k = 0; k < 16; k++) {
            float4 a = *(const float4*)&As[k * 64 + r0];
            float4 bb = *(const float4*)&Bs[k * 64 + c0];
            float av[4] = {a.x, a.y, a.z, a.w}, bv[4] = {bb.x, bb.y, bb.z, bb.w};
#pragma unroll
            for (int i = 0; i < 4; i++)
#pragma unroll
                for (int j = 0; j < 4; j++) acc[i][j] += av[i] * bv[j];
        }
        __syncthreads();
    }
#pragma unroll
    for (int i = 0; i < 4; i++)
#pragma unroll
        for (int j = 0; j < 4; j++)
            d_aggin[n * 131072 + (rowBase + r0 + i) * 128 + colBase + c0 + j] = acc[i][j];
}

// ---------- K6: sub LN + expansion ----------
__global__ __launch_bounds__(128) void k_subexpand(const float* __restrict__ lg,
                                                   const float* __restrict__ lb) {
    __shared__ float sh[128];
    int bx = blockIdx.x, t = threadIdx.x;
    int n = bx >> 10;
    float v = d_aggin[bx * 128 + t];
    float S = red128(v, sh), Q = red128(v * v, sh);
    float mean = S * (1.f / 128.f);
    float rstd = rsqrtf(Q * (1.f / 128.f) - mean * mean + 1e-3f);
    float xn = (v - mean) * rstd * lg[n * 128 + t] + lb[n * 128 + t];
    float e[9];
    kan_expand(xn, e);
    size_t base = (size_t)bx * 1152 + t * 9;
#pragma unroll
    for (int j = 0; j < 9; j++) d_subE[base + j] = e[j];
}

// ---------- K7: pack sub weights ----------
__global__ void k_packW(const float* __restrict__ bw, const float* __restrict__ sw) {
    int idx = blockIdx.x * 256 + threadIdx.x;
    if (idx >= 3 * 1152 * 128) return;
    int n = idx / 147456, rem = idx - n * 147456;
    int k = rem >> 7, o = rem & 127;
    int f = k / 9, j = k - f * 9;
    d_subW[idx] = (j == 0) ? bw[n * 16384 + f * 128 + o]
                           : sw[n * 131072 + (f * 8 + j - 1) * 128 + o];
}

// ---------- K8: sub GEMM + epilogue ----------
__global__ __launch_bounds__(256) void k_subgemm(const float* __restrict__ ss,
                                                 const float* __restrict__ subk,
                                                 float* __restrict__ out_ss) {
    __shared__ float As[16 * 64], Bs[16 * 64];
    int tid = threadIdx.x, n = blockIdx.z;
    int rowBase = blockIdx.y * 64, colBase = blockIdx.x * 64;
    int r0 = (tid >> 4) * 4, c0 = (tid & 15) * 4;
    float acc[4][4] = {};
    for (int kt = 0; kt < 1152; kt += 16) {
        for (int idx = tid; idx < 1024; idx += 256) {
            int kk = idx & 15, m = idx >> 4, b = rowBase + m;
            As[kk * 64 + m] = d_subE[((size_t)(n * 1024 + b)) * 1152 + kt + kk];
            int cc = idx & 63, k2 = idx >> 6, c = colBase + cc;
            Bs[k2 * 64 + cc] = d_subW[n * 147456 + (kt + k2) * 128 + c];
        }
        __syncthreads();
#pragma unroll
        for (int k = 0; k < 16; k++) {
            float4 a = *(const float4*)&As[k * 64 + r0];
            float4 bb = *(const float4*)&Bs[k * 64 + c0];
            float av[4] = {a.x, a.y, a.z, a.w}, bv[4] = {bb.x, bb.y, bb.z, bb.w};
#pragma unroll
            for (int i = 0; i < 4; i++)
#pragma unroll
                for (int j = 0; j < 4; j++) acc[i][j] += av[i] * bv[j];
        }
        __syncthreads();
    }
#pragma unroll
    for (int i = 0; i < 4; i++)
#pragma unroll
        for (int j = 0; j < 4; j++) {
            int b = rowBase + r0 + i, o = colBase + c0 + j;
            float v = acc[i][j] * d_sigw[b * 3 + n];
            d_agg[b * 384 + n * 128 + o] = v;
            out_ss[n * 131072 + b * 128 + o] =
                subk[n * 256 + o] * v + ss[n * 131072 + b * 128 + o] * subk[n * 256 + 128 + o];
        }
}

// ---------- K9: x_o GEMM + final c, h ----------
__global__ __launch_bounds__(256) void k_final(const float* __restrict__ aw, const float* __restrict__ ab,
                                               const float* __restrict__ c0p, float* __restrict__ out) {
    __shared__ float As[16 * 64], Bs[16 * 64];
    int tid = threadIdx.x;
    int rowBase = blockIdx.y * 64, colBase = blockIdx.x * 64;
    int r0 = (tid >> 4) * 4, cc0 = (tid & 15) * 4;
    float acc[4][4] = {};
    for (int kt = 0; kt < 384; kt += 16) {
        for (int idx = tid; idx < 1024; idx += 256) {
            int kk = idx & 15, m = idx >> 4;
            As[kk * 64 + m] = d_agg[(rowBase + m) * 384 + kt + kk];
            int cc = idx & 63, k2 = idx >> 6;
            Bs[k2 * 64 + cc] = aw[(kt + k2) * 512 + colBase + cc];
        }
        __syncthreads();
#pragma unroll
        for (int k = 0; k < 16; k++) {
            float4 a = *(const float4*)&As[k * 64 + r0];
            float4 bb = *(const float4*)&Bs[k * 64 + cc0];
            float av[4] = {a.x, a.y, a.z, a.w}, bv[4] = {bb.x, bb.y, bb.z, bb.w};
#pragma unroll
            for (int i = 0; i < 4; i++)
#pragma unroll
                for (int j = 0; j < 4; j++) acc[i][j] += av[i] * bv[j];
        }
        __syncthreads();
    }
#pragma unroll
    for (int i = 0; i < 4; i++)
#pragma unroll
        for (int j = 0; j < 4; j++) {
            int b = rowBase + r0 + i, c = colBase + cc0 + j;
            float xo = sigm(acc[i][j] + ab[c]);
            float zi = d_z[b * 1536 + c];
            float zf = d_z[b * 1536 + 512 + c];
            float zc = d_z[b * 1536 + 1024 + c];
            float cv = zf * c0p[b * 512 + c] + zi * zc;
            out[b * 512 + c] = xo * tanhf(cv);
            out[B_ * U_ + b * 512 + c] = cv;
        }
}

// ---------- launch ----------
extern "C" void kernel_launch(void* const* d_in, const int* in_sizes, int n_in,
                              void* d_out, int out_size) {
    const float* inputs   = (const float*)d_in[0];
    const float* h0       = (const float*)d_in[1];
    const float* c0       = (const float*)d_in[2];
    const float* sub_st   = (const float*)d_in[3];
    const float* kern     = (const float*)d_in[4];
    const float* rkern    = (const float*)d_in[5];
    const float* bias     = (const float*)d_in[6];
    const float* sub_k    = (const float*)d_in[7];
    const float* sub_rki  = (const float*)d_in[8];
    const float* sub_rks  = (const float*)d_in[9];
    const float* agg_w    = (const float*)d_in[10];
    const float* agg_b    = (const float*)d_in[11];
    const float* sub_lng  = (const float*)d_in[12];
    const float* sub_lnb  = (const float*)d_in[13];
    const float* sub_bw   = (const float*)d_in[14];
    const float* sub_sw   = (const float*)d_in[15];
    const float* g_skw    = (const float*)d_in[16];
    const float* g_skb    = (const float*)d_in[17];
    const float* k1_lng   = (const float*)d_in[18];
    const float* k1_lnb   = (const float*)d_in[19];
    const float* k1_base  = (const float*)d_in[20];
    const float* k1_spl   = (const float*)d_in[21];
    const float* k2_lng   = (const float*)d_in[22];
    const float* k2_lnb   = (const float*)d_in[23];
    const float* k2_base  = (const float*)d_in[24];
    const float* k2_spl   = (const float*)d_in[25];
    const float* gw       = (const float*)d_in[26];
    const float* gb       = (const float*)d_in[27];
    const float* sw       = (const float*)d_in[28];
    const float* sb       = (const float*)d_in[29];
    const float* lg       = (const float*)d_in[30];
    const float* lb       = (const float*)d_in[31];
    float* out = (float*)d_out;

    static bool attr_set = false;
    if (!attr_set) {
        cudaFuncSetAttribute(k_mma, cudaFuncAttributeMaxDynamicSharedMemorySize, SM_MMA);
        attr_set = true;
    }

    k_stats<<<B_, 128>>>(inputs, g_skw, g_skb);
    k_mma<<<dim3(8, 8, 4), 256, SM_MMA>>>(inputs, k1_lng, k1_lnb, k1_base, k1_spl);
    k_red<<<2048, 256>>>();
    k_head<<<B_, 128>>>(k2_lng, k2_lnb, k2_base, k2_spl, gw, gb, sw, sb, lg, lb);
    k_z<<<dim3(24, 16), 256>>>(inputs, h0, kern, rkern, bias);
    k_aggin<<<dim3(2, 16, 3), 256>>>(inputs, sub_st, sub_rki, sub_rks);
    k_subexpand<<<3 * B_, 128>>>(sub_lng, sub_lnb);
    k_packW<<<(3 * 1152 * 128 + 255) / 256, 256>>>(sub_bw, sub_sw);
    k_subgemm<<<dim3(2, 16, 3), 256>>>(sub_st, sub_k, out + 2 * B_ * U_);
    k_final<<<dim3(8, 16), 256>>>(agg_w, agg_b, c0, out);
}